// round 12
// baseline (speedup 1.0000x reference)
#include <cuda_runtime.h>
#include <cuda_fp16.h>
#include <cstdint>
#include <math.h>

// VectorQuantizer: z_e (16,256,1024) f32, emb (8192,256) f32
// out = [ quantized (16,256,1024), vq_loss, perplexity ]  (f32)

#define Bv 16
#define Dv 256
#define Tv 1024
#define Kv 8192
#define Nv 16384
#define BDT (Bv*Dv*Tv)

// fp16 1-term (xhi*ehi): pairwise comparison error std ~9e-3; TAU=0.05 ~ 5.5 sigma
#define TAU 0.05f

// ---------------- device scratch ----------------
__device__ __align__(16) __half g_xhi[(size_t)Nv * Dv];
__device__ __align__(16) float  g_xf [(size_t)Nv * Dv];
__device__ __align__(16) __half g_ehi[(size_t)Kv * Dv];
__device__ __align__(16) float g_eT[(size_t)Dv * Kv];   // transposed codebook (f32)
__device__ __align__(16) float g_h[Kv];
__device__ __align__(16) float g_xsq[Nv];
__device__ __align__(16) float g_m[Nv];
__device__ __align__(16) int   g_idx[Nv];
__device__ __align__(16) float g_cnt[Kv];
__device__ int g_nflag;
__device__ __align__(16) int g_flags[Nv];
__device__ __align__(16) unsigned long long g_key[Nv];
// per-K-half partial results from k_mma
__device__ __align__(16) float g_hb1[2 * Nv];
__device__ __align__(16) float g_hb2[2 * Nv];
__device__ __align__(16) int   g_hbk[2 * Nv];

// ---------------- helpers ----------------
__device__ __forceinline__ uint32_t smem_u32(const void* p) {
    uint32_t a;
    asm("{ .reg .u64 t; cvta.to.shared.u64 t, %1; cvt.u32.u64 %0, t; }" : "=r"(a) : "l"(p));
    return a;
}
#define SW(o) ((o) ^ ((((uint32_t)(o)) >> 3) & 0x70u))

#define LDMX4(r, a) \
    asm volatile("ldmatrix.sync.aligned.m8n8.x4.shared.b16 {%0,%1,%2,%3}, [%4];" \
        : "=r"((r)[0]), "=r"((r)[1]), "=r"((r)[2]), "=r"((r)[3]) : "r"(a))

#define MMA16816(c, a, b0, b1) \
    asm volatile("mma.sync.aligned.m16n8k16.row.col.f32.f16.f16.f32 " \
        "{%0,%1,%2,%3}, {%4,%5,%6,%7}, {%8,%9}, {%0,%1,%2,%3};" \
        : "+f"((c)[0]), "+f"((c)[1]), "+f"((c)[2]), "+f"((c)[3]) \
        : "r"((a)[0]), "r"((a)[1]), "r"((a)[2]), "r"((a)[3]), "r"(b0), "r"(b1))

#define CP16(dst, src) \
    asm volatile("cp.async.cg.shared.global [%0], [%1], 16;" :: "r"(dst), "l"(src))
#define CP_COMMIT() asm volatile("cp.async.commit_group;" ::: "memory")
#define CP_WAIT0()  asm volatile("cp.async.wait_group 0;" ::: "memory")

// monotonic float -> uint map (order preserving)
__device__ __forceinline__ uint32_t fmono(float f) {
    uint32_t u = __float_as_uint(f);
    return (u & 0x80000000u) ? ~u : (u | 0x80000000u);
}

// ---------------- prep: emb -> ehi + eT + half norms + zero cnt/flag (one read) ----------------
__global__ void k_prep_e(const float* __restrict__ emb) {
    __shared__ float tile[32][257];
    int k0 = blockIdx.x * 32;
    int tid = threadIdx.x;
    for (int i = tid; i < 32 * Dv; i += 256) {
        int r = i >> 8, d = i & 255;
        tile[r][d] = emb[(size_t)(k0 + r) * Dv + d];
    }
    __syncthreads();
    // half norms: 8 threads per code
    {
        int c = tid >> 3, p = tid & 7;
        const float* row = &tile[c][p * 32];
        float s = 0.f;
#pragma unroll
        for (int d = 0; d < 32; d++) s += row[d] * row[d];
#pragma unroll
        for (int o = 4; o; o >>= 1) s += __shfl_xor_sync(0xffffffffu, s, o);
        if (p == 0) {
            g_h[k0 + c] = 0.5f * s;
            g_cnt[k0 + c] = 0.f;
        }
    }
    if (blockIdx.x == 0 && tid == 0) g_nflag = 0;
    // write ehi (fp16 pairs)
    for (int i = tid; i < 32 * 128; i += 256) {
        int r = i >> 7, d2 = i & 127;
        __half2 h2 = __floats2half2_rn(tile[r][d2 * 2], tile[r][d2 * 2 + 1]);
        ((__half2*)g_ehi)[(size_t)(k0 + r) * (Dv / 2) + d2] = h2;
    }
    // write eT (transposed f32): thread (tx,ty): conflict-free stride-257 reads
    {
        int tx = tid & 31, ty = tid >> 5;
#pragma unroll 4
        for (int j = 0; j < 32; j++) {
            int d = ty * 32 + j;
            g_eT[(size_t)d * Kv + k0 + tx] = tile[tx][d];
        }
    }
}

// ---------------- prep: transpose z -> x[n][d] f32 + fp16 hi ----------------
__global__ void k_split_x(const float* __restrict__ z) {
    __shared__ float tile[64][65];
    int t0 = blockIdx.x * 64, d0 = blockIdx.y * 64, b = blockIdx.z;
    const float* src = z + ((size_t)b * Dv + d0) * Tv + t0;
    for (int i = threadIdx.x; i < 1024; i += 256) {
        int dd = i >> 4, tq = i & 15;
        float4 v = *(const float4*)(src + (size_t)dd * Tv + tq * 4);
        tile[dd][tq * 4 + 0] = v.x; tile[dd][tq * 4 + 1] = v.y;
        tile[dd][tq * 4 + 2] = v.z; tile[dd][tq * 4 + 3] = v.w;
    }
    __syncthreads();
    int n0 = b * Tv + t0;
    for (int i = threadIdx.x; i < 1024; i += 256) {
        int tt = i >> 4, dq = i & 15;
        float y[4];
#pragma unroll
        for (int c = 0; c < 4; c++) y[c] = tile[dq * 4 + c][tt];
        size_t o = (size_t)(n0 + tt) * Dv + d0 + dq * 4;
        *(float4*)(g_xf + o) = make_float4(y[0], y[1], y[2], y[3]);
        __half hi[4];
#pragma unroll
        for (int c = 0; c < 4; c++) hi[c] = __float2half_rn(y[c]);
        *(uint2*)(g_xhi + o) = *(uint2*)hi;
    }
}

// ---------------- main: 64-row x half-K CTAs, 2 CTAs/SM, fp16 1-term GEMM + argmax ----------------
// blockIdx.x: row-tile = bid>>1 (64 rows), K-half = bid&1 (32 k-tiles of 128 codes).
// Warp w: row-group rg=w>>2 (rows rg*32..+31), col-group cg=w&3 (cols cg*32..+31).
// smem: A [0,32K): 4 d-blocks x [64r][64d] SW128; B double buffer [32K,64K): 2 x 16KB.
#define SM_B   32768
#define SMEM_SZ (65536 + 1024 + 1024)

__global__ __launch_bounds__(256, 2) void k_mma() {
    extern __shared__ char smraw[];
    uint32_t raw = smem_u32(smraw);
    uint32_t sb = (raw + 1023u) & ~1023u;
    char* smp = smraw + (sb - raw);
    const int tid = threadIdx.x, wid = tid >> 5, lane = tid & 31;
    const int n0 = (blockIdx.x >> 1) * 64;
    const int khalf = blockIdx.x & 1;
    const int kt0 = khalf * 32;
    const int glast = (kt0 + 32) * 4 - 1;
    const int rg = wid >> 2, cg = wid & 3;
    const int g = lane >> 2, tg = lane & 3;

    // stage A: Xhi, 4 d-blocks of [64r][64 fp16] SW128 (2048 16B units)
    for (int u = tid; u < 2048; u += 256) {
        int c = u >> 9, r = (u >> 3) & 63, q = u & 7;
        size_t so = (size_t)(n0 + r) * Dv + c * 64 + q * 8;
        *(uint4*)(smp + c * 8192 + SW(r * 128 + q * 16)) = *(const uint4*)(g_xhi + so);
    }

    const int m = lane >> 3, j7 = lane & 7;
    uint32_t arow[2];
#pragma unroll
    for (int s = 0; s < 2; s++)
        arow[s] = (uint32_t)(rg * 32 + s * 16 + (m & 1) * 8 + j7) * 128;
    const uint32_t ach   = (uint32_t)(lane >> 4) * 16;
    const uint32_t bbase = (uint32_t)(cg * 32 + (m >> 1) * 8 + j7) * 128 + (uint32_t)(m & 1) * 16;

    // cp.async chunk loader: absolute chunk gidx = kt*4 + c -> buf gidx&1 (16KB)
    auto load_chunk = [&](int gidx) {
        int kt = gidx >> 2, c = gidx & 3;
        uint32_t bb = sb + SM_B + (gidx & 1) * 16384;
        const __half* sh = g_ehi + (size_t)(kt * 128) * Dv + c * 64;
#pragma unroll
        for (int j = 0; j < 4; j++) {
            int i = tid + 256 * j;
            int row = i >> 3, q = i & 7;
            CP16(bb + SW(row * 128 + q * 16), sh + (size_t)row * Dv + q * 8);
        }
    };

    load_chunk(kt0 * 4);
    CP_COMMIT();
    CP_WAIT0();
    __syncthreads();

    // trackers: 4 rows per thread
    float best[4]  = { -3.4e38f, -3.4e38f, -3.4e38f, -3.4e38f };
    float best2[4] = { -3.4e38f, -3.4e38f, -3.4e38f, -3.4e38f };
    int   bk[4]    = { 0, 0, 0, 0 };

    uint32_t A[2][2][4];   // [buf][stripe][4]
    uint32_t Bf[2][2][4];  // [buf][ntile][4]

#pragma unroll 1
    for (int kt = kt0; kt < kt0 + 32; kt++) {
        float acc[8][4];
#pragma unroll
        for (int i = 0; i < 8; i++)
#pragma unroll
            for (int q = 0; q < 4; q++) acc[i][q] = 0.f;

#pragma unroll 1
        for (int c = 0; c < 4; c++) {
            int gi = kt * 4 + c;
            if (gi < glast) { load_chunk(gi + 1); CP_COMMIT(); }

            const uint32_t abase = sb + c * 8192;
            const uint32_t bB = sb + SM_B + (gi & 1) * 16384;

            // preload ds=0 fragments
#pragma unroll
            for (int s = 0; s < 2; s++)
                LDMX4(A[0][s], abase + SW(arow[s] + ach));
#pragma unroll
            for (int nt = 0; nt < 2; nt++)
                LDMX4(Bf[0][nt], bB + SW(bbase + nt * 2048));

#pragma unroll
            for (int ds = 0; ds < 4; ds++) {
                const int ab = ds & 1;
                if (ds < 3) {
#pragma unroll
                    for (int s = 0; s < 2; s++)
                        LDMX4(A[ab ^ 1][s], abase + SW(arow[s] + (ds + 1) * 32 + ach));
#pragma unroll
                    for (int nt = 0; nt < 2; nt++)
                        LDMX4(Bf[ab ^ 1][nt], bB + SW(bbase + nt * 2048 + (ds + 1) * 32));
                }
#pragma unroll
                for (int s = 0; s < 2; s++)
#pragma unroll
                    for (int nt = 0; nt < 2; nt++) {
                        MMA16816(acc[s * 4 + nt * 2],     A[ab][s], Bf[ab][nt][0], Bf[ab][nt][1]);
                        MMA16816(acc[s * 4 + nt * 2 + 1], A[ab][s], Bf[ab][nt][2], Bf[ab][nt][3]);
                    }
            }
            if (gi < glast) CP_WAIT0();
            __syncthreads();
        }

        // epilogue: fold this 128-col tile (32 cols for this warp) into trackers
#pragma unroll
        for (int s = 0; s < 2; s++)
#pragma unroll
            for (int nt = 0; nt < 2; nt++)
#pragma unroll
                for (int j = 0; j < 2; j++) {
                    int t = s * 4 + nt * 2 + j;
                    int col = kt * 128 + cg * 32 + nt * 16 + j * 8 + 2 * tg;
                    float h0 = __ldg(g_h + col), h1 = __ldg(g_h + col + 1);
                    int r0 = s * 2, r1 = s * 2 + 1;
                    float v00 = acc[t][0] - h0, v01 = acc[t][1] - h1;
                    float v10 = acc[t][2] - h0, v11 = acc[t][3] - h1;
                    if (v00 > best[r0]) { best2[r0] = best[r0]; best[r0] = v00; bk[r0] = col; }
                    else if (v00 > best2[r0]) best2[r0] = v00;
                    if (v01 > best[r0]) { best2[r0] = best[r0]; best[r0] = v01; bk[r0] = col + 1; }
                    else if (v01 > best2[r0]) best2[r0] = v01;
                    if (v10 > best[r1]) { best2[r1] = best[r1]; best[r1] = v10; bk[r1] = col; }
                    else if (v10 > best2[r1]) best2[r1] = v10;
                    if (v11 > best[r1]) { best2[r1] = best[r1]; best[r1] = v11; bk[r1] = col + 1; }
                    else if (v11 > best2[r1]) best2[r1] = v11;
                }
    }

    // reduce across the 4 lanes (tg) sharing each row
#pragma unroll
    for (int r = 0; r < 4; r++) {
#pragma unroll
        for (int o = 1; o <= 2; o <<= 1) {
            float ob = __shfl_xor_sync(0xffffffffu, best[r], o);
            float os = __shfl_xor_sync(0xffffffffu, best2[r], o);
            int   ok = __shfl_xor_sync(0xffffffffu, bk[r], o);
            if (ob > best[r] || (ob == best[r] && ok < bk[r])) {
                best2[r] = fmaxf(best[r], os);
                best[r] = ob; bk[r] = ok;
            } else {
                best2[r] = fmaxf(best2[r], ob);
            }
        }
    }

    // cross-warp (col-group) merge via smem: fb/fs/fk [4][64]
    __syncthreads();
    float* fb = (float*)smp;
    float* fs = fb + 256;
    int*   fk = (int*)(fs + 256);
    if (tg == 0) {
#pragma unroll
        for (int r = 0; r < 4; r++) {
            int row = rg * 32 + (r >> 1) * 16 + g + (r & 1) * 8;
            fb[cg * 64 + row] = best[r];
            fs[cg * 64 + row] = best2[r];
            fk[cg * 64 + row] = bk[r];
        }
    }
    __syncthreads();
    if (tid < 64) {
        float bb = fb[tid], ss = fs[tid];
        int kk = fk[tid];
#pragma unroll
        for (int c2 = 1; c2 < 4; c2++) {
            float ob = fb[c2 * 64 + tid], os = fs[c2 * 64 + tid];
            int ok = fk[c2 * 64 + tid];
            if (ob > bb || (ob == bb && ok < kk)) { ss = fmaxf(bb, os); bb = ob; kk = ok; }
            else ss = fmaxf(ss, ob);
        }
        size_t o = (size_t)khalf * Nv + n0 + tid;
        g_hb1[o] = bb;
        g_hb2[o] = ss;
        g_hbk[o] = kk;
    }
}

// ---------------- merge K-halves -> g_idx + flags ----------------
__global__ void k_merge() {
    int n = blockIdx.x * 256 + threadIdx.x;
    float a1 = g_hb1[n], a2 = g_hb2[n];
    int   ak = g_hbk[n];
    float c1 = g_hb1[Nv + n], c2 = g_hb2[Nv + n];
    int   ck = g_hbk[Nv + n];
    float bb, ss; int kk;
    if (a1 >= c1) { bb = a1; kk = ak; ss = fmaxf(a2, c1); }   // tie -> half 0 (lower k)
    else          { bb = c1; kk = ck; ss = fmaxf(c2, a1); }
    g_idx[n] = kk;
    if (bb - ss < TAU) {
        g_key[n] = 0ull;
        int pos = atomicAdd(&g_nflag, 1);
        g_flags[pos] = n;
    }
}

// ---------------- batched exact rescore: (16-row batch) x (K/4 slice) per work item ----------------
#define RB 16
__global__ void k_rescore() {
    __shared__ float sx[RB][Dv];
    __shared__ int   sn[RB];
    __shared__ unsigned long long rk[256];
    int tid = threadIdx.x;
    int nf = g_nflag; if (nf > Nv) nf = Nv;
    if (nf <= 0) return;
    int nbatch = (nf + RB - 1) / RB;
    int nwork = nbatch * 4;
    for (int w = blockIdx.x; w < nwork; w += gridDim.x) {
        int bi = w >> 2, kq = w & 3;
        int r0 = bi * RB;
        int nr = nf - r0; if (nr > RB) nr = RB;
        if (tid < RB) sn[tid] = g_flags[r0 + (tid < nr ? tid : 0)];
        __syncthreads();
        for (int i = tid; i < RB * Dv; i += 256) {
            int r = i >> 8, d = i & 255;
            sx[r][d] = g_xf[(size_t)sn[r] * Dv + d];
        }
        __syncthreads();

        float best[RB]; int bkk[RB];
#pragma unroll
        for (int r = 0; r < RB; r++) { best[r] = -3.4e38f; bkk[r] = 0; }

#pragma unroll 1
        for (int i = 0; i < 8; i++) {
            int k = kq * 2048 + i * 256 + tid;
            float s[RB];
#pragma unroll
            for (int r = 0; r < RB; r++) s[r] = 0.f;
            const float* ep = g_eT + k;
#pragma unroll 4
            for (int d4 = 0; d4 < 64; d4++) {
                float e0 = ep[(size_t)(4 * d4 + 0) * Kv];
                float e1 = ep[(size_t)(4 * d4 + 1) * Kv];
                float e2 = ep[(size_t)(4 * d4 + 2) * Kv];
                float e3 = ep[(size_t)(4 * d4 + 3) * Kv];
#pragma unroll
                for (int r = 0; r < RB; r++) {
                    float4 xv = *(const float4*)&sx[r][d4 * 4];
                    s[r] = fmaf(xv.x, e0, fmaf(xv.y, e1, fmaf(xv.z, e2, fmaf(xv.w, e3, s[r]))));
                }
            }
            float hk = g_h[k];
#pragma unroll
            for (int r = 0; r < RB; r++) {
                float v = s[r] - hk;
                if (v > best[r]) { best[r] = v; bkk[r] = k; }
            }
        }

#pragma unroll 1
        for (int r = 0; r < RB; r++) {
            rk[tid] = ((unsigned long long)fmono(best[r]) << 32)
                    | (unsigned long long)(0xFFFFFFFFu - (uint32_t)bkk[r]);
            __syncthreads();
            for (int o = 128; o; o >>= 1) {
                if (tid < o) { if (rk[tid + o] > rk[tid]) rk[tid] = rk[tid + o]; }
                __syncthreads();
            }
            if (tid == 0 && r < nr) atomicMax(&g_key[sn[r]], rk[0]);
            __syncthreads();
        }
        __syncthreads();
    }
}

// ---------------- decode rescore keys into g_idx ----------------
__global__ void k_fix() {
    int nf = g_nflag; if (nf > Nv) nf = Nv;
    for (int f = blockIdx.x * 256 + threadIdx.x; f < nf; f += gridDim.x * 256) {
        int n = g_flags[f];
        unsigned long long key = g_key[n];
        g_idx[n] = (int)(0xFFFFFFFFu - (uint32_t)(key & 0xFFFFFFFFull));
    }
}

// ---------------- post: exact g_m/xsq + histogram + scatter (one emb gather) ----------------
__global__ void k_post(const float* __restrict__ emb, float* __restrict__ out) {
    __shared__ float tile[32][257];
    __shared__ int sidx[32];
    int n0 = blockIdx.x * 32;
    int b = n0 >> 10, t0 = n0 & 1023;
    int tid = threadIdx.x;
    if (tid < 32) sidx[tid] = g_idx[n0 + tid];
    __syncthreads();
    for (int i = tid; i < 32 * Dv; i += 256) {
        int r = i >> 8, d = i & 255;
        tile[r][d] = emb[(size_t)sidx[r] * Dv + d];
    }
    __syncthreads();

    int w = tid >> 5, lane = tid & 31;
#pragma unroll 1
    for (int j = 0; j < 4; j++) {
        int r = w * 4 + j;
        int n = n0 + r;
        const float* x = g_xf + (size_t)n * Dv + lane * 8;
        float4 x0 = *(const float4*)(x), x1 = *(const float4*)(x + 4);
        const float* e = &tile[r][lane * 8];
        float s = x0.x * e[0] + x0.y * e[1] + x0.z * e[2] + x0.w * e[3]
                + x1.x * e[4] + x1.y * e[5] + x1.z * e[6] + x1.w * e[7];
        float q = x0.x * x0.x + x0.y * x0.y + x0.z * x0.z + x0.w * x0.w
                + x1.x * x1.x + x1.y * x1.y + x1.z * x1.z + x1.w * x1.w;
#pragma unroll
        for (int t = 16; t; t >>= 1) {
            s += __shfl_xor_sync(0xffffffffu, s, t);
            q += __shfl_xor_sync(0xffffffffu, q, t);
        }
        if (lane == 0) {
            g_m[n] = s - g_h[sidx[r]];
            g_xsq[n] = q;
            atomicAdd(&g_cnt[sidx[r]], 1.0f);
        }
    }

    // scatter transposed out (tile unchanged)
    float* ob = out + (size_t)b * Dv * Tv + t0;
    for (int i = tid; i < 32 * Dv; i += 256) {
        int d = i >> 5, r = i & 31;
        ob[(size_t)d * Tv + r] = tile[r][d];
    }
}

// ---------------- scalars ----------------
__global__ void k_final(float* __restrict__ out, int out_size) {
    __shared__ double sd[256];
    int tid = threadIdx.x;
    double s = 0.0;
    for (int n = tid; n < Nv; n += 256)
        s += (double)g_xsq[n] - 2.0 * (double)g_m[n];
    double e = 0.0;
    for (int k = tid; k < Kv; k += 256) {
        double p = (double)g_cnt[k] * (1.0 / (double)Nv);
        e += p * log(p + 1e-10);
    }
    sd[tid] = s; __syncthreads();
    for (int o = 128; o; o >>= 1) { if (tid < o) sd[tid] += sd[tid + o]; __syncthreads(); }
    double loss = 0.25 * sd[0] / ((double)Nv * (double)Dv);
    __syncthreads();
    sd[tid] = e; __syncthreads();
    for (int o = 128; o; o >>= 1) { if (tid < o) sd[tid] += sd[tid + o]; __syncthreads(); }
    if (tid == 0 && out_size >= BDT + 2) {
        out[BDT]     = (float)loss;
        out[BDT + 1] = (float)exp(-sd[0]);
    }
}

// ---------------- launch ----------------
extern "C" void kernel_launch(void* const* d_in, const int* in_sizes, int n_in,
                              void* d_out, int out_size) {
    const float* z   = (const float*)d_in[0];
    const float* emb = (const float*)d_in[1];
    float* out = (float*)d_out;

    cudaFuncSetAttribute(k_mma, cudaFuncAttributeMaxDynamicSharedMemorySize, SMEM_SZ);

    k_prep_e <<<Kv / 32, 256>>>(emb);
    k_split_x<<<dim3(Tv / 64, Dv / 64, Bv), 256>>>(z);
    k_mma    <<<Nv / 32, 256, SMEM_SZ>>>();     // 512 CTAs: (row-tile, K-half)
    k_merge  <<<Nv / 256, 256>>>();
    k_rescore<<<128, 256>>>();
    k_fix    <<<16, 256>>>();
    k_post   <<<Nv / 32, 256>>>(emb, out);
    k_final  <<<1, 256>>>(out, out_size);
}

// round 13
// speedup vs baseline: 1.0320x; 1.0320x over previous
#include <cuda_runtime.h>
#include <cuda_fp16.h>
#include <cstdint>
#include <math.h>

// VectorQuantizer: z_e (16,256,1024) f32, emb (8192,256) f32
// out = [ quantized (16,256,1024), vq_loss, perplexity ]  (f32)

#define Bv 16
#define Dv 256
#define Tv 1024
#define Kv 8192
#define Nv 16384
#define BDT (Bv*Dv*Tv)

// fp16 1-term (xhi*ehi): pairwise comparison error std ~9e-3; TAU=0.05 ~ 5.5 sigma
#define TAU 0.05f

// ---------------- device scratch ----------------
__device__ __align__(16) __half g_xhi[(size_t)Nv * Dv];
__device__ __align__(16) float  g_xf [(size_t)Nv * Dv];
__device__ __align__(16) __half g_ehi[(size_t)Kv * Dv];
__device__ __align__(16) float g_eT[(size_t)Dv * Kv];   // transposed codebook (f32)
__device__ __align__(16) float g_h[Kv];
__device__ __align__(16) float g_xsq[Nv];
__device__ __align__(16) float g_m[Nv];
__device__ __align__(16) int   g_idx[Nv];
__device__ __align__(16) float g_cnt[Kv];
__device__ int g_nflag;
__device__ __align__(16) int g_flags[Nv];
__device__ __align__(16) unsigned long long g_key[Nv];

// ---------------- helpers ----------------
__device__ __forceinline__ uint32_t smem_u32(const void* p) {
    uint32_t a;
    asm("{ .reg .u64 t; cvta.to.shared.u64 t, %1; cvt.u32.u64 %0, t; }" : "=r"(a) : "l"(p));
    return a;
}
#define SW(o) ((o) ^ ((((uint32_t)(o)) >> 3) & 0x70u))

#define LDMX4(r, a) \
    asm volatile("ldmatrix.sync.aligned.m8n8.x4.shared.b16 {%0,%1,%2,%3}, [%4];" \
        : "=r"((r)[0]), "=r"((r)[1]), "=r"((r)[2]), "=r"((r)[3]) : "r"(a))

#define MMA16816(c, a, b0, b1) \
    asm volatile("mma.sync.aligned.m16n8k16.row.col.f32.f16.f16.f32 " \
        "{%0,%1,%2,%3}, {%4,%5,%6,%7}, {%8,%9}, {%0,%1,%2,%3};" \
        : "+f"((c)[0]), "+f"((c)[1]), "+f"((c)[2]), "+f"((c)[3]) \
        : "r"((a)[0]), "r"((a)[1]), "r"((a)[2]), "r"((a)[3]), "r"(b0), "r"(b1))

#define CP16(dst, src) \
    asm volatile("cp.async.cg.shared.global [%0], [%1], 16;" :: "r"(dst), "l"(src))
#define CP_COMMIT() asm volatile("cp.async.commit_group;" ::: "memory")
#define CP_WAIT0()  asm volatile("cp.async.wait_group 0;" ::: "memory")

// monotonic float -> uint map (order preserving)
__device__ __forceinline__ uint32_t fmono(float f) {
    uint32_t u = __float_as_uint(f);
    return (u & 0x80000000u) ? ~u : (u | 0x80000000u);
}

// ---------------- prep: emb -> ehi + eT + half norms + zero cnt/flag (one read) ----------------
__global__ void k_prep_e(const float* __restrict__ emb) {
    __shared__ float tile[32][257];
    int k0 = blockIdx.x * 32;
    int tid = threadIdx.x;
    for (int i = tid; i < 32 * Dv; i += 256) {
        int r = i >> 8, d = i & 255;
        tile[r][d] = emb[(size_t)(k0 + r) * Dv + d];
    }
    __syncthreads();
    // half norms: 8 threads per code
    {
        int c = tid >> 3, p = tid & 7;
        const float* row = &tile[c][p * 32];
        float s = 0.f;
#pragma unroll
        for (int d = 0; d < 32; d++) s += row[d] * row[d];
#pragma unroll
        for (int o = 4; o; o >>= 1) s += __shfl_xor_sync(0xffffffffu, s, o);
        if (p == 0) {
            g_h[k0 + c] = 0.5f * s;
            g_cnt[k0 + c] = 0.f;
        }
    }
    if (blockIdx.x == 0 && tid == 0) g_nflag = 0;
    // write ehi (fp16 pairs)
    for (int i = tid; i < 32 * 128; i += 256) {
        int r = i >> 7, d2 = i & 127;
        __half2 h2 = __floats2half2_rn(tile[r][d2 * 2], tile[r][d2 * 2 + 1]);
        ((__half2*)g_ehi)[(size_t)(k0 + r) * (Dv / 2) + d2] = h2;
    }
    // write eT (transposed f32)
    {
        int tx = tid & 31, ty = tid >> 5;
#pragma unroll 4
        for (int j = 0; j < 32; j++) {
            int d = ty * 32 + j;
            g_eT[(size_t)d * Kv + k0 + tx] = tile[tx][d];
        }
    }
}

// ---------------- prep: transpose z -> x[n][d] f32 + fp16 hi ----------------
__global__ void k_split_x(const float* __restrict__ z) {
    __shared__ float tile[64][65];
    int t0 = blockIdx.x * 64, d0 = blockIdx.y * 64, b = blockIdx.z;
    const float* src = z + ((size_t)b * Dv + d0) * Tv + t0;
    for (int i = threadIdx.x; i < 1024; i += 256) {
        int dd = i >> 4, tq = i & 15;
        float4 v = *(const float4*)(src + (size_t)dd * Tv + tq * 4);
        tile[dd][tq * 4 + 0] = v.x; tile[dd][tq * 4 + 1] = v.y;
        tile[dd][tq * 4 + 2] = v.z; tile[dd][tq * 4 + 3] = v.w;
    }
    __syncthreads();
    int n0 = b * Tv + t0;
    for (int i = threadIdx.x; i < 1024; i += 256) {
        int tt = i >> 4, dq = i & 15;
        float y[4];
#pragma unroll
        for (int c = 0; c < 4; c++) y[c] = tile[dq * 4 + c][tt];
        size_t o = (size_t)(n0 + tt) * Dv + d0 + dq * 4;
        *(float4*)(g_xf + o) = make_float4(y[0], y[1], y[2], y[3]);
        __half hi[4];
#pragma unroll
        for (int c = 0; c < 4; c++) hi[c] = __float2half_rn(y[c]);
        *(uint2*)(g_xhi + o) = *(uint2*)hi;
    }
}

// ---------------- main: 64-row CTAs, 2 CTAs/SM, fp16 1-term GEMM + fused argmax ----------------
// Warp w: row-group rg=w>>2 (rows rg*32..+31), col-group cg=w&3 (cols cg*32..+31).
// smem: A [0,32K): 4 d-blocks x [64r][64d] SW128 (8KB each);
//       B double buffer [32K,64K): 2 x 16KB chunks ([128 codes][64d]) via cp.async.
#define SM_B   32768
#define SMEM_SZ (65536 + 1024 + 1024)

__global__ __launch_bounds__(256, 2) void k_mma() {
    extern __shared__ char smraw[];
    uint32_t raw = smem_u32(smraw);
    uint32_t sb = (raw + 1023u) & ~1023u;
    char* smp = smraw + (sb - raw);
    const int tid = threadIdx.x, wid = tid >> 5, lane = tid & 31;
    const int n0 = blockIdx.x * 64;
    const int rg = wid >> 2, cg = wid & 3;
    const int g = lane >> 2, tg = lane & 3;

    // stage A: Xhi, 4 d-blocks of [64r][64 fp16] SW128 (2048 16B units)
    for (int u = tid; u < 2048; u += 256) {
        int c = u >> 9, r = (u >> 3) & 63, q = u & 7;
        size_t so = (size_t)(n0 + r) * Dv + c * 64 + q * 8;
        *(uint4*)(smp + c * 8192 + SW(r * 128 + q * 16)) = *(const uint4*)(g_xhi + so);
    }

    const int m = lane >> 3, j7 = lane & 7;
    uint32_t arow[2];
#pragma unroll
    for (int s = 0; s < 2; s++)
        arow[s] = (uint32_t)(rg * 32 + s * 16 + (m & 1) * 8 + j7) * 128;
    const uint32_t ach   = (uint32_t)(lane >> 4) * 16;
    const uint32_t bbase = (uint32_t)(cg * 32 + (m >> 1) * 8 + j7) * 128 + (uint32_t)(m & 1) * 16;

    // cp.async chunk loader: chunk gidx = kt*4 + c -> buf gidx&1 (16KB)
    auto load_chunk = [&](int gidx) {
        int kt = gidx >> 2, c = gidx & 3;
        uint32_t bb = sb + SM_B + (gidx & 1) * 16384;
        const __half* sh = g_ehi + (size_t)(kt * 128) * Dv + c * 64;
#pragma unroll
        for (int j = 0; j < 4; j++) {
            int i = tid + 256 * j;
            int row = i >> 3, q = i & 7;
            CP16(bb + SW(row * 128 + q * 16), sh + (size_t)row * Dv + q * 8);
        }
    };

    load_chunk(0);
    CP_COMMIT();
    CP_WAIT0();
    __syncthreads();

    // trackers: 4 rows per thread: r = s*2+half -> row rg*32 + s*16 + g + half*8
    float best[4]  = { -3.4e38f, -3.4e38f, -3.4e38f, -3.4e38f };
    float best2[4] = { -3.4e38f, -3.4e38f, -3.4e38f, -3.4e38f };
    int   bk[4]    = { 0, 0, 0, 0 };

    uint32_t A[2][2][4];   // [buf][stripe][4]
    uint32_t Bf[2][2][4];  // [buf][ntile][4]

#pragma unroll 1
    for (int kt = 0; kt < 64; kt++) {
        float acc[8][4];
#pragma unroll
        for (int i = 0; i < 8; i++)
#pragma unroll
            for (int q = 0; q < 4; q++) acc[i][q] = 0.f;

#pragma unroll 1
        for (int c = 0; c < 4; c++) {
            int gi = kt * 4 + c;
            if (gi < 255) { load_chunk(gi + 1); CP_COMMIT(); }

            const uint32_t abase = sb + c * 8192;
            const uint32_t bB = sb + SM_B + (gi & 1) * 16384;

            // preload ds=0 fragments
#pragma unroll
            for (int s = 0; s < 2; s++)
                LDMX4(A[0][s], abase + SW(arow[s] + ach));
#pragma unroll
            for (int nt = 0; nt < 2; nt++)
                LDMX4(Bf[0][nt], bB + SW(bbase + nt * 2048));

#pragma unroll
            for (int ds = 0; ds < 4; ds++) {
                const int ab = ds & 1;
                // prefetch ds+1 fragments while issuing ds MMAs
                if (ds < 3) {
#pragma unroll
                    for (int s = 0; s < 2; s++)
                        LDMX4(A[ab ^ 1][s], abase + SW(arow[s] + (ds + 1) * 32 + ach));
#pragma unroll
                    for (int nt = 0; nt < 2; nt++)
                        LDMX4(Bf[ab ^ 1][nt], bB + SW(bbase + nt * 2048 + (ds + 1) * 32));
                }
                // 8 MMAs
#pragma unroll
                for (int s = 0; s < 2; s++)
#pragma unroll
                    for (int nt = 0; nt < 2; nt++) {
                        MMA16816(acc[s * 4 + nt * 2],     A[ab][s], Bf[ab][nt][0], Bf[ab][nt][1]);
                        MMA16816(acc[s * 4 + nt * 2 + 1], A[ab][s], Bf[ab][nt][2], Bf[ab][nt][3]);
                    }
            }
            if (gi < 255) CP_WAIT0();
            __syncthreads();
        }

        // epilogue: fold this 128-col tile (32 cols for this warp) into trackers
#pragma unroll
        for (int s = 0; s < 2; s++)
#pragma unroll
            for (int nt = 0; nt < 2; nt++)
#pragma unroll
                for (int j = 0; j < 2; j++) {
                    int t = s * 4 + nt * 2 + j;
                    int col = kt * 128 + cg * 32 + nt * 16 + j * 8 + 2 * tg;
                    float h0 = __ldg(g_h + col), h1 = __ldg(g_h + col + 1);
                    int r0 = s * 2, r1 = s * 2 + 1;
                    float v00 = acc[t][0] - h0, v01 = acc[t][1] - h1;
                    float v10 = acc[t][2] - h0, v11 = acc[t][3] - h1;
                    if (v00 > best[r0]) { best2[r0] = best[r0]; best[r0] = v00; bk[r0] = col; }
                    else if (v00 > best2[r0]) best2[r0] = v00;
                    if (v01 > best[r0]) { best2[r0] = best[r0]; best[r0] = v01; bk[r0] = col + 1; }
                    else if (v01 > best2[r0]) best2[r0] = v01;
                    if (v10 > best[r1]) { best2[r1] = best[r1]; best[r1] = v10; bk[r1] = col; }
                    else if (v10 > best2[r1]) best2[r1] = v10;
                    if (v11 > best[r1]) { best2[r1] = best[r1]; best[r1] = v11; bk[r1] = col + 1; }
                    else if (v11 > best2[r1]) best2[r1] = v11;
                }
    }

    // reduce across the 4 lanes (tg) sharing each row
#pragma unroll
    for (int r = 0; r < 4; r++) {
#pragma unroll
        for (int o = 1; o <= 2; o <<= 1) {
            float ob = __shfl_xor_sync(0xffffffffu, best[r], o);
            float os = __shfl_xor_sync(0xffffffffu, best2[r], o);
            int   ok = __shfl_xor_sync(0xffffffffu, bk[r], o);
            if (ob > best[r] || (ob == best[r] && ok < bk[r])) {
                best2[r] = fmaxf(best[r], os);
                best[r] = ob; bk[r] = ok;
            } else {
                best2[r] = fmaxf(best2[r], ob);
            }
        }
    }

    // cross-warp (col-group) merge via smem: fb/fs/fk [4][64]
    __syncthreads();
    float* fb = (float*)smp;
    float* fs = fb + 256;
    int*   fk = (int*)(fs + 256);
    if (tg == 0) {
#pragma unroll
        for (int r = 0; r < 4; r++) {
            int row = rg * 32 + (r >> 1) * 16 + g + (r & 1) * 8;
            fb[cg * 64 + row] = best[r];
            fs[cg * 64 + row] = best2[r];
            fk[cg * 64 + row] = bk[r];
        }
    }
    __syncthreads();
    if (tid < 64) {
        float bb = fb[tid], ss = fs[tid];
        int kk = fk[tid];
#pragma unroll
        for (int c2 = 1; c2 < 4; c2++) {
            float ob = fb[c2 * 64 + tid], os = fs[c2 * 64 + tid];
            int ok = fk[c2 * 64 + tid];
            if (ob > bb || (ob == bb && ok < kk)) { ss = fmaxf(bb, os); bb = ob; kk = ok; }
            else ss = fmaxf(ss, ob);
        }
        int n = n0 + tid;
        g_idx[n] = kk;
        if (bb - ss < TAU) {
            g_key[n] = 0ull;
            int pos = atomicAdd(&g_nflag, 1);
            g_flags[pos] = n;
        }
    }
}

// ---------------- batched exact rescore: (16-row batch) x (K/4 slice) per work item ----------------
#define RB 16
__global__ void k_rescore() {
    __shared__ float sx[RB][Dv];
    __shared__ int   sn[RB];
    __shared__ unsigned long long rk[256];
    int tid = threadIdx.x;
    int nf = g_nflag; if (nf > Nv) nf = Nv;
    if (nf <= 0) return;
    int nbatch = (nf + RB - 1) / RB;
    int nwork = nbatch * 4;
    for (int w = blockIdx.x; w < nwork; w += gridDim.x) {
        int bi = w >> 2, kq = w & 3;
        int r0 = bi * RB;
        int nr = nf - r0; if (nr > RB) nr = RB;
        if (tid < RB) sn[tid] = g_flags[r0 + (tid < nr ? tid : 0)];
        __syncthreads();
        for (int i = tid; i < RB * Dv; i += 256) {
            int r = i >> 8, d = i & 255;
            sx[r][d] = g_xf[(size_t)sn[r] * Dv + d];
        }
        __syncthreads();

        float best[RB]; int bkk[RB];
#pragma unroll
        for (int r = 0; r < RB; r++) { best[r] = -3.4e38f; bkk[r] = 0; }

#pragma unroll 1
        for (int i = 0; i < 8; i++) {
            int k = kq * 2048 + i * 256 + tid;
            float s[RB];
#pragma unroll
            for (int r = 0; r < RB; r++) s[r] = 0.f;
            const float* ep = g_eT + k;
#pragma unroll 4
            for (int d4 = 0; d4 < 64; d4++) {
                float e0 = ep[(size_t)(4 * d4 + 0) * Kv];
                float e1 = ep[(size_t)(4 * d4 + 1) * Kv];
                float e2 = ep[(size_t)(4 * d4 + 2) * Kv];
                float e3 = ep[(size_t)(4 * d4 + 3) * Kv];
#pragma unroll
                for (int r = 0; r < RB; r++) {
                    float4 xv = *(const float4*)&sx[r][d4 * 4];
                    s[r] = fmaf(xv.x, e0, fmaf(xv.y, e1, fmaf(xv.z, e2, fmaf(xv.w, e3, s[r]))));
                }
            }
            float hk = g_h[k];
#pragma unroll
            for (int r = 0; r < RB; r++) {
                float v = s[r] - hk;
                if (v > best[r]) { best[r] = v; bkk[r] = k; }
            }
        }

#pragma unroll 1
        for (int r = 0; r < RB; r++) {
            rk[tid] = ((unsigned long long)fmono(best[r]) << 32)
                    | (unsigned long long)(0xFFFFFFFFu - (uint32_t)bkk[r]);
            __syncthreads();
            for (int o = 128; o; o >>= 1) {
                if (tid < o) { if (rk[tid + o] > rk[tid]) rk[tid] = rk[tid + o]; }
                __syncthreads();
            }
            if (tid == 0 && r < nr) atomicMax(&g_key[sn[r]], rk[0]);
            __syncthreads();
        }
        __syncthreads();
    }
}

// ---------------- decode rescore keys into g_idx ----------------
__global__ void k_fix() {
    int nf = g_nflag; if (nf > Nv) nf = Nv;
    for (int f = blockIdx.x * 256 + threadIdx.x; f < nf; f += gridDim.x * 256) {
        int n = g_flags[f];
        unsigned long long key = g_key[n];
        g_idx[n] = (int)(0xFFFFFFFFu - (uint32_t)(key & 0xFFFFFFFFull));
    }
}

// ---------------- post: exact g_m/xsq + histogram + scatter (one emb gather) ----------------
__global__ void k_post(const float* __restrict__ emb, float* __restrict__ out) {
    __shared__ float tile[32][257];
    __shared__ int sidx[32];
    int n0 = blockIdx.x * 32;
    int b = n0 >> 10, t0 = n0 & 1023;
    int tid = threadIdx.x;
    if (tid < 32) sidx[tid] = g_idx[n0 + tid];
    __syncthreads();
    for (int i = tid; i < 32 * Dv; i += 256) {
        int r = i >> 8, d = i & 255;
        tile[r][d] = emb[(size_t)sidx[r] * Dv + d];
    }
    __syncthreads();

    int w = tid >> 5, lane = tid & 31;
#pragma unroll 1
    for (int j = 0; j < 4; j++) {
        int r = w * 4 + j;
        int n = n0 + r;
        const float* x = g_xf + (size_t)n * Dv + lane * 8;
        float4 x0 = *(const float4*)(x), x1 = *(const float4*)(x + 4);
        const float* e = &tile[r][lane * 8];
        float s = x0.x * e[0] + x0.y * e[1] + x0.z * e[2] + x0.w * e[3]
                + x1.x * e[4] + x1.y * e[5] + x1.z * e[6] + x1.w * e[7];
        float q = x0.x * x0.x + x0.y * x0.y + x0.z * x0.z + x0.w * x0.w
                + x1.x * x1.x + x1.y * x1.y + x1.z * x1.z + x1.w * x1.w;
#pragma unroll
        for (int t = 16; t; t >>= 1) {
            s += __shfl_xor_sync(0xffffffffu, s, t);
            q += __shfl_xor_sync(0xffffffffu, q, t);
        }
        if (lane == 0) {
            g_m[n] = s - g_h[sidx[r]];
            g_xsq[n] = q;
            atomicAdd(&g_cnt[sidx[r]], 1.0f);
        }
    }

    // scatter transposed out (tile unchanged)
    float* ob = out + (size_t)b * Dv * Tv + t0;
    for (int i = tid; i < 32 * Dv; i += 256) {
        int d = i >> 5, r = i & 31;
        ob[(size_t)d * Tv + r] = tile[r][d];
    }
}

// ---------------- scalars ----------------
__global__ void k_final(float* __restrict__ out, int out_size) {
    __shared__ double sd[256];
    int tid = threadIdx.x;
    double s = 0.0;
    for (int n = tid; n < Nv; n += 256)
        s += (double)g_xsq[n] - 2.0 * (double)g_m[n];
    double e = 0.0;
    for (int k = tid; k < Kv; k += 256) {
        double p = (double)g_cnt[k] * (1.0 / (double)Nv);
        e += p * log(p + 1e-10);
    }
    sd[tid] = s; __syncthreads();
    for (int o = 128; o; o >>= 1) { if (tid < o) sd[tid] += sd[tid + o]; __syncthreads(); }
    double loss = 0.25 * sd[0] / ((double)Nv * (double)Dv);
    __syncthreads();
    sd[tid] = e; __syncthreads();
    for (int o = 128; o; o >>= 1) { if (tid < o) sd[tid] += sd[tid + o]; __syncthreads(); }
    if (tid == 0 && out_size >= BDT + 2) {
        out[BDT]     = (float)loss;
        out[BDT + 1] = (float)exp(-sd[0]);
    }
}

// ---------------- launch ----------------
extern "C" void kernel_launch(void* const* d_in, const int* in_sizes, int n_in,
                              void* d_out, int out_size) {
    const float* z   = (const float*)d_in[0];
    const float* emb = (const float*)d_in[1];
    float* out = (float*)d_out;

    cudaFuncSetAttribute(k_mma, cudaFuncAttributeMaxDynamicSharedMemorySize, SMEM_SZ);

    k_prep_e <<<Kv / 32, 256>>>(emb);
    k_split_x<<<dim3(Tv / 64, Dv / 64, Bv), 256>>>(z);
    k_mma    <<<Nv / 64, 256, SMEM_SZ>>>();
    k_rescore<<<128, 256>>>();
    k_fix    <<<16, 256>>>();
    k_post   <<<Nv / 32, 256>>>(emb, out);
    k_final  <<<1, 256>>>(out, out_size);
}

// round 14
// speedup vs baseline: 1.4085x; 1.3649x over previous
#include <cuda_runtime.h>
#include <cuda_fp16.h>
#include <cstdint>
#include <math.h>

// VectorQuantizer: z_e (16,256,1024) f32, emb (8192,256) f32
// out = [ quantized (16,256,1024), vq_loss, perplexity ]  (f32)

#define Bv 16
#define Dv 256
#define Tv 1024
#define Kv 8192
#define Nv 16384
#define BDT (Bv*Dv*Tv)

// fp16 1-term (xhi*ehi): pairwise comparison error std ~9e-3; TAU=0.05 ~ 5.5 sigma
#define TAU 0.05f

// ---------------- device scratch ----------------
__device__ __align__(16) __half g_xhi[(size_t)Nv * Dv];
__device__ __align__(16) float  g_xf [(size_t)Nv * Dv];
__device__ __align__(16) __half g_ehi[(size_t)Kv * Dv];
__device__ __align__(16) float g_eT[(size_t)Dv * Kv];   // transposed codebook (f32)
__device__ __align__(16) float g_h[Kv];
__device__ __align__(16) float g_xsq[Nv];
__device__ __align__(16) float g_m[Nv];
__device__ __align__(16) int   g_idx[Nv];
__device__ __align__(16) float g_cnt[Kv];
__device__ int g_nflag;
__device__ __align__(16) int g_flags[Nv];
__device__ __align__(16) unsigned long long g_key[Nv];

// ---------------- helpers ----------------
__device__ __forceinline__ uint32_t smem_u32(const void* p) {
    uint32_t a;
    asm("{ .reg .u64 t; cvta.to.shared.u64 t, %1; cvt.u32.u64 %0, t; }" : "=r"(a) : "l"(p));
    return a;
}
#define SW(o) ((o) ^ ((((uint32_t)(o)) >> 3) & 0x70u))

#define LDMX4(r, a) \
    asm volatile("ldmatrix.sync.aligned.m8n8.x4.shared.b16 {%0,%1,%2,%3}, [%4];" \
        : "=r"((r)[0]), "=r"((r)[1]), "=r"((r)[2]), "=r"((r)[3]) : "r"(a))

#define MMA16816(c, a, b0, b1) \
    asm volatile("mma.sync.aligned.m16n8k16.row.col.f32.f16.f16.f32 " \
        "{%0,%1,%2,%3}, {%4,%5,%6,%7}, {%8,%9}, {%0,%1,%2,%3};" \
        : "+f"((c)[0]), "+f"((c)[1]), "+f"((c)[2]), "+f"((c)[3]) \
        : "r"((a)[0]), "r"((a)[1]), "r"((a)[2]), "r"((a)[3]), "r"(b0), "r"(b1))

#define CP16(dst, src) \
    asm volatile("cp.async.cg.shared.global [%0], [%1], 16;" :: "r"(dst), "l"(src))
#define CP_COMMIT() asm volatile("cp.async.commit_group;" ::: "memory")
#define CP_WAIT0()  asm volatile("cp.async.wait_group 0;" ::: "memory")

// monotonic float -> uint map (order preserving)
__device__ __forceinline__ uint32_t fmono(float f) {
    uint32_t u = __float_as_uint(f);
    return (u & 0x80000000u) ? ~u : (u | 0x80000000u);
}

// ---------------- prep: emb -> ehi + eT + half norms + zero cnt/flag (one read) ----------------
__global__ void k_prep_e(const float* __restrict__ emb) {
    __shared__ float tile[32][257];
    int k0 = blockIdx.x * 32;
    int tid = threadIdx.x;
    for (int i = tid; i < 32 * Dv; i += 256) {
        int r = i >> 8, d = i & 255;
        tile[r][d] = emb[(size_t)(k0 + r) * Dv + d];
    }
    __syncthreads();
    // half norms: 8 threads per code
    {
        int c = tid >> 3, p = tid & 7;
        const float* row = &tile[c][p * 32];
        float s = 0.f;
#pragma unroll
        for (int d = 0; d < 32; d++) s += row[d] * row[d];
#pragma unroll
        for (int o = 4; o; o >>= 1) s += __shfl_xor_sync(0xffffffffu, s, o);
        if (p == 0) {
            g_h[k0 + c] = 0.5f * s;
            g_cnt[k0 + c] = 0.f;
        }
    }
    if (blockIdx.x == 0 && tid == 0) g_nflag = 0;
    // write ehi (fp16 pairs)
    for (int i = tid; i < 32 * 128; i += 256) {
        int r = i >> 7, d2 = i & 127;
        __half2 h2 = __floats2half2_rn(tile[r][d2 * 2], tile[r][d2 * 2 + 1]);
        ((__half2*)g_ehi)[(size_t)(k0 + r) * (Dv / 2) + d2] = h2;
    }
    // write eT (transposed f32)
    {
        int tx = tid & 31, ty = tid >> 5;
#pragma unroll 4
        for (int j = 0; j < 32; j++) {
            int d = ty * 32 + j;
            g_eT[(size_t)d * Kv + k0 + tx] = tile[tx][d];
        }
    }
}

// ---------------- prep: transpose z -> x[n][d] f32 + fp16 hi ----------------
__global__ void k_split_x(const float* __restrict__ z) {
    __shared__ float tile[64][65];
    int t0 = blockIdx.x * 64, d0 = blockIdx.y * 64, b = blockIdx.z;
    const float* src = z + ((size_t)b * Dv + d0) * Tv + t0;
    for (int i = threadIdx.x; i < 1024; i += 256) {
        int dd = i >> 4, tq = i & 15;
        float4 v = *(const float4*)(src + (size_t)dd * Tv + tq * 4);
        tile[dd][tq * 4 + 0] = v.x; tile[dd][tq * 4 + 1] = v.y;
        tile[dd][tq * 4 + 2] = v.z; tile[dd][tq * 4 + 3] = v.w;
    }
    __syncthreads();
    int n0 = b * Tv + t0;
    for (int i = threadIdx.x; i < 1024; i += 256) {
        int tt = i >> 4, dq = i & 15;
        float y[4];
#pragma unroll
        for (int c = 0; c < 4; c++) y[c] = tile[dq * 4 + c][tt];
        size_t o = (size_t)(n0 + tt) * Dv + d0 + dq * 4;
        *(float4*)(g_xf + o) = make_float4(y[0], y[1], y[2], y[3]);
        __half hi[4];
#pragma unroll
        for (int c = 0; c < 4; c++) hi[c] = __float2half_rn(y[c]);
        *(uint2*)(g_xhi + o) = *(uint2*)hi;
    }
}

// ---------------- main: 64-row CTAs, 2 CTAs/SM, fp16 1-term GEMM + fused argmax ----------------
// Warp w: row-group rg=w>>2 (rows rg*32..+31), col-group cg=w&3 (cols cg*32..+31).
// smem: A [0,32K): 4 d-blocks x [64r][64d] SW128 (8KB each);
//       B double buffer [32K,64K): 2 x 16KB chunks ([128 codes][64d]) via cp.async.
#define SM_B   32768
#define SMEM_SZ (65536 + 1024 + 1024)

__global__ __launch_bounds__(256, 2) void k_mma() {
    extern __shared__ char smraw[];
    uint32_t raw = smem_u32(smraw);
    uint32_t sb = (raw + 1023u) & ~1023u;
    char* smp = smraw + (sb - raw);
    const int tid = threadIdx.x, wid = tid >> 5, lane = tid & 31;
    const int n0 = blockIdx.x * 64;
    const int rg = wid >> 2, cg = wid & 3;
    const int g = lane >> 2, tg = lane & 3;

    // stage A: Xhi, 4 d-blocks of [64r][64 fp16] SW128 (2048 16B units)
    for (int u = tid; u < 2048; u += 256) {
        int c = u >> 9, r = (u >> 3) & 63, q = u & 7;
        size_t so = (size_t)(n0 + r) * Dv + c * 64 + q * 8;
        *(uint4*)(smp + c * 8192 + SW(r * 128 + q * 16)) = *(const uint4*)(g_xhi + so);
    }

    const int m = lane >> 3, j7 = lane & 7;
    uint32_t arow[2];
#pragma unroll
    for (int s = 0; s < 2; s++)
        arow[s] = (uint32_t)(rg * 32 + s * 16 + (m & 1) * 8 + j7) * 128;
    const uint32_t ach   = (uint32_t)(lane >> 4) * 16;
    const uint32_t bbase = (uint32_t)(cg * 32 + (m >> 1) * 8 + j7) * 128 + (uint32_t)(m & 1) * 16;

    // cp.async chunk loader: chunk gidx = kt*4 + c -> buf gidx&1 (16KB)
    auto load_chunk = [&](int gidx) {
        int kt = gidx >> 2, c = gidx & 3;
        uint32_t bb = sb + SM_B + (gidx & 1) * 16384;
        const __half* sh = g_ehi + (size_t)(kt * 128) * Dv + c * 64;
#pragma unroll
        for (int j = 0; j < 4; j++) {
            int i = tid + 256 * j;
            int row = i >> 3, q = i & 7;
            CP16(bb + SW(row * 128 + q * 16), sh + (size_t)row * Dv + q * 8);
        }
    };

    load_chunk(0);
    CP_COMMIT();
    CP_WAIT0();
    __syncthreads();

    // trackers: 4 rows per thread: r = s*2+half -> row rg*32 + s*16 + g + half*8
    float best[4]  = { -3.4e38f, -3.4e38f, -3.4e38f, -3.4e38f };
    float best2[4] = { -3.4e38f, -3.4e38f, -3.4e38f, -3.4e38f };
    int   bk[4]    = { 0, 0, 0, 0 };

    uint32_t A[2][2][4];   // [buf][stripe][4]
    uint32_t Bf[2][2][4];  // [buf][ntile][4]

#pragma unroll 1
    for (int kt = 0; kt < 64; kt++) {
        float acc[8][4];
#pragma unroll
        for (int i = 0; i < 8; i++)
#pragma unroll
            for (int q = 0; q < 4; q++) acc[i][q] = 0.f;

#pragma unroll 1
        for (int c = 0; c < 4; c++) {
            int gi = kt * 4 + c;
            if (gi < 255) { load_chunk(gi + 1); CP_COMMIT(); }

            const uint32_t abase = sb + c * 8192;
            const uint32_t bB = sb + SM_B + (gi & 1) * 16384;

            // preload ds=0 fragments
#pragma unroll
            for (int s = 0; s < 2; s++)
                LDMX4(A[0][s], abase + SW(arow[s] + ach));
#pragma unroll
            for (int nt = 0; nt < 2; nt++)
                LDMX4(Bf[0][nt], bB + SW(bbase + nt * 2048));

#pragma unroll
            for (int ds = 0; ds < 4; ds++) {
                const int ab = ds & 1;
                // prefetch ds+1 fragments while issuing ds MMAs
                if (ds < 3) {
#pragma unroll
                    for (int s = 0; s < 2; s++)
                        LDMX4(A[ab ^ 1][s], abase + SW(arow[s] + (ds + 1) * 32 + ach));
#pragma unroll
                    for (int nt = 0; nt < 2; nt++)
                        LDMX4(Bf[ab ^ 1][nt], bB + SW(bbase + nt * 2048 + (ds + 1) * 32));
                }
                // 8 MMAs
#pragma unroll
                for (int s = 0; s < 2; s++)
#pragma unroll
                    for (int nt = 0; nt < 2; nt++) {
                        MMA16816(acc[s * 4 + nt * 2],     A[ab][s], Bf[ab][nt][0], Bf[ab][nt][1]);
                        MMA16816(acc[s * 4 + nt * 2 + 1], A[ab][s], Bf[ab][nt][2], Bf[ab][nt][3]);
                    }
            }
            if (gi < 255) CP_WAIT0();
            __syncthreads();
        }

        // epilogue: fold this 128-col tile (32 cols for this warp) into trackers
#pragma unroll
        for (int s = 0; s < 2; s++)
#pragma unroll
            for (int nt = 0; nt < 2; nt++)
#pragma unroll
                for (int j = 0; j < 2; j++) {
                    int t = s * 4 + nt * 2 + j;
                    int col = kt * 128 + cg * 32 + nt * 16 + j * 8 + 2 * tg;
                    float h0 = __ldg(g_h + col), h1 = __ldg(g_h + col + 1);
                    int r0 = s * 2, r1 = s * 2 + 1;
                    float v00 = acc[t][0] - h0, v01 = acc[t][1] - h1;
                    float v10 = acc[t][2] - h0, v11 = acc[t][3] - h1;
                    if (v00 > best[r0]) { best2[r0] = best[r0]; best[r0] = v00; bk[r0] = col; }
                    else if (v00 > best2[r0]) best2[r0] = v00;
                    if (v01 > best[r0]) { best2[r0] = best[r0]; best[r0] = v01; bk[r0] = col + 1; }
                    else if (v01 > best2[r0]) best2[r0] = v01;
                    if (v10 > best[r1]) { best2[r1] = best[r1]; best[r1] = v10; bk[r1] = col; }
                    else if (v10 > best2[r1]) best2[r1] = v10;
                    if (v11 > best[r1]) { best2[r1] = best[r1]; best[r1] = v11; bk[r1] = col + 1; }
                    else if (v11 > best2[r1]) best2[r1] = v11;
                }
    }

    // reduce across the 4 lanes (tg) sharing each row
#pragma unroll
    for (int r = 0; r < 4; r++) {
#pragma unroll
        for (int o = 1; o <= 2; o <<= 1) {
            float ob = __shfl_xor_sync(0xffffffffu, best[r], o);
            float os = __shfl_xor_sync(0xffffffffu, best2[r], o);
            int   ok = __shfl_xor_sync(0xffffffffu, bk[r], o);
            if (ob > best[r] || (ob == best[r] && ok < bk[r])) {
                best2[r] = fmaxf(best[r], os);
                best[r] = ob; bk[r] = ok;
            } else {
                best2[r] = fmaxf(best2[r], ob);
            }
        }
    }

    // cross-warp (col-group) merge via smem: fb/fs/fk [4][64]
    __syncthreads();
    float* fb = (float*)smp;
    float* fs = fb + 256;
    int*   fk = (int*)(fs + 256);
    if (tg == 0) {
#pragma unroll
        for (int r = 0; r < 4; r++) {
            int row = rg * 32 + (r >> 1) * 16 + g + (r & 1) * 8;
            fb[cg * 64 + row] = best[r];
            fs[cg * 64 + row] = best2[r];
            fk[cg * 64 + row] = bk[r];
        }
    }
    __syncthreads();
    if (tid < 64) {
        float bb = fb[tid], ss = fs[tid];
        int kk = fk[tid];
#pragma unroll
        for (int c2 = 1; c2 < 4; c2++) {
            float ob = fb[c2 * 64 + tid], os = fs[c2 * 64 + tid];
            int ok = fk[c2 * 64 + tid];
            if (ob > bb || (ob == bb && ok < kk)) { ss = fmaxf(bb, os); bb = ob; kk = ok; }
            else ss = fmaxf(ss, ob);
        }
        int n = n0 + tid;
        g_idx[n] = kk;
        if (bb - ss < TAU) {
            g_key[n] = 0ull;
            int pos = atomicAdd(&g_nflag, 1);
            g_flags[pos] = n;
        }
    }
}

// ---------------- rescore v3: (16-row batch) x (K/16 slice = 512 codes) per work item ----------------
// Thread owns 2 codes x 16 rows = 32 fp32 chains; e-loads double-buffered one d4-step ahead.
#define RB 16
__global__ __launch_bounds__(256, 2) void k_rescore() {
    __shared__ float sx[RB][Dv];
    __shared__ int   sn[RB];
    __shared__ unsigned long long wm[8];
    int tid = threadIdx.x, wid = tid >> 5, lane = tid & 31;
    int nf = g_nflag; if (nf > Nv) nf = Nv;
    if (nf <= 0) return;
    int nbatch = (nf + RB - 1) / RB;
    int nwork = nbatch * 16;
    for (int w = blockIdx.x; w < nwork; w += gridDim.x) {
        int bi = w >> 4, ks = w & 15;
        int r0 = bi * RB;
        int nr = nf - r0; if (nr > RB) nr = RB;
        if (tid < RB) sn[tid] = g_flags[r0 + (tid < nr ? tid : 0)];
        __syncthreads();
        for (int i = tid; i < RB * (Dv / 4); i += 256) {
            int r = i >> 6, d = i & 63;
            *(float4*)&sx[r][d * 4] = *(const float4*)(g_xf + (size_t)sn[r] * Dv + d * 4);
        }
        __syncthreads();

        const int kA = ks * 512 + tid;
        const int kB = kA + 256;
        const float* epA = g_eT + kA;
        const float* epB = g_eT + kB;
        float sA[RB], sB[RB];
#pragma unroll
        for (int r = 0; r < RB; r++) { sA[r] = 0.f; sB[r] = 0.f; }

        float ea[2][4], eb[2][4];
#pragma unroll
        for (int c = 0; c < 4; c++) {
            ea[0][c] = epA[(size_t)c * Kv];
            eb[0][c] = epB[(size_t)c * Kv];
        }
#pragma unroll 2
        for (int d4 = 0; d4 < 64; d4++) {
            int pb = d4 & 1;
            if (d4 < 63) {
#pragma unroll
                for (int c = 0; c < 4; c++) {
                    ea[pb ^ 1][c] = epA[(size_t)((d4 + 1) * 4 + c) * Kv];
                    eb[pb ^ 1][c] = epB[(size_t)((d4 + 1) * 4 + c) * Kv];
                }
            }
#pragma unroll
            for (int r = 0; r < RB; r++) {
                float4 xv = *(const float4*)&sx[r][d4 * 4];
                sA[r] = fmaf(xv.x, ea[pb][0], fmaf(xv.y, ea[pb][1],
                          fmaf(xv.z, ea[pb][2], fmaf(xv.w, ea[pb][3], sA[r]))));
                sB[r] = fmaf(xv.x, eb[pb][0], fmaf(xv.y, eb[pb][1],
                          fmaf(xv.z, eb[pb][2], fmaf(xv.w, eb[pb][3], sB[r]))));
            }
        }

        float hA = g_h[kA], hB = g_h[kB];
#pragma unroll 1
        for (int r = 0; r < RB; r++) {
            if (r >= nr) break;
            float vA = sA[r] - hA, vB = sB[r] - hB;
            float v; int kk;
            if (vA >= vB) { v = vA; kk = kA; } else { v = vB; kk = kB; }
            unsigned long long key = ((unsigned long long)fmono(v) << 32)
                                   | (unsigned long long)(0xFFFFFFFFu - (uint32_t)kk);
#pragma unroll
            for (int o = 16; o; o >>= 1) {
                unsigned long long ok = __shfl_xor_sync(0xffffffffu, key, o);
                if (ok > key) key = ok;
            }
            if (lane == 0) wm[wid] = key;
            __syncthreads();
            if (tid == 0) {
                unsigned long long b = wm[0];
#pragma unroll
                for (int w2 = 1; w2 < 8; w2++) if (wm[w2] > b) b = wm[w2];
                atomicMax(&g_key[sn[r]], b);
            }
            __syncthreads();
        }
        __syncthreads();
    }
}

// ---------------- decode rescore keys into g_idx ----------------
__global__ void k_fix() {
    int nf = g_nflag; if (nf > Nv) nf = Nv;
    for (int f = blockIdx.x * 256 + threadIdx.x; f < nf; f += gridDim.x * 256) {
        int n = g_flags[f];
        unsigned long long key = g_key[n];
        g_idx[n] = (int)(0xFFFFFFFFu - (uint32_t)(key & 0xFFFFFFFFull));
    }
}

// ---------------- post: exact g_m/xsq + histogram + scatter (one emb gather) ----------------
__global__ void k_post(const float* __restrict__ emb, float* __restrict__ out) {
    __shared__ float tile[32][257];
    __shared__ int sidx[32];
    int n0 = blockIdx.x * 32;
    int b = n0 >> 10, t0 = n0 & 1023;
    int tid = threadIdx.x;
    if (tid < 32) sidx[tid] = g_idx[n0 + tid];
    __syncthreads();
    for (int i = tid; i < 32 * Dv; i += 256) {
        int r = i >> 8, d = i & 255;
        tile[r][d] = emb[(size_t)sidx[r] * Dv + d];
    }
    __syncthreads();

    int w = tid >> 5, lane = tid & 31;
#pragma unroll 1
    for (int j = 0; j < 4; j++) {
        int r = w * 4 + j;
        int n = n0 + r;
        const float* x = g_xf + (size_t)n * Dv + lane * 8;
        float4 x0 = *(const float4*)(x), x1 = *(const float4*)(x + 4);
        const float* e = &tile[r][lane * 8];
        float s = x0.x * e[0] + x0.y * e[1] + x0.z * e[2] + x0.w * e[3]
                + x1.x * e[4] + x1.y * e[5] + x1.z * e[6] + x1.w * e[7];
        float q = x0.x * x0.x + x0.y * x0.y + x0.z * x0.z + x0.w * x0.w
                + x1.x * x1.x + x1.y * x1.y + x1.z * x1.z + x1.w * x1.w;
#pragma unroll
        for (int t = 16; t; t >>= 1) {
            s += __shfl_xor_sync(0xffffffffu, s, t);
            q += __shfl_xor_sync(0xffffffffu, q, t);
        }
        if (lane == 0) {
            g_m[n] = s - g_h[sidx[r]];
            g_xsq[n] = q;
            atomicAdd(&g_cnt[sidx[r]], 1.0f);
        }
    }

    // scatter transposed out (tile unchanged)
    float* ob = out + (size_t)b * Dv * Tv + t0;
    for (int i = tid; i < 32 * Dv; i += 256) {
        int d = i >> 5, r = i & 31;
        ob[(size_t)d * Tv + r] = tile[r][d];
    }
}

// ---------------- scalars ----------------
__global__ void k_final(float* __restrict__ out, int out_size) {
    __shared__ double sd[256];
    int tid = threadIdx.x;
    double s = 0.0;
    for (int n = tid; n < Nv; n += 256)
        s += (double)g_xsq[n] - 2.0 * (double)g_m[n];
    double e = 0.0;
    for (int k = tid; k < Kv; k += 256) {
        double p = (double)g_cnt[k] * (1.0 / (double)Nv);
        e += p * log(p + 1e-10);
    }
    sd[tid] = s; __syncthreads();
    for (int o = 128; o; o >>= 1) { if (tid < o) sd[tid] += sd[tid + o]; __syncthreads(); }
    double loss = 0.25 * sd[0] / ((double)Nv * (double)Dv);
    __syncthreads();
    sd[tid] = e; __syncthreads();
    for (int o = 128; o; o >>= 1) { if (tid < o) sd[tid] += sd[tid + o]; __syncthreads(); }
    if (tid == 0 && out_size >= BDT + 2) {
        out[BDT]     = (float)loss;
        out[BDT + 1] = (float)exp(-sd[0]);
    }
}

// ---------------- launch ----------------
extern "C" void kernel_launch(void* const* d_in, const int* in_sizes, int n_in,
                              void* d_out, int out_size) {
    const float* z   = (const float*)d_in[0];
    const float* emb = (const float*)d_in[1];
    float* out = (float*)d_out;

    cudaFuncSetAttribute(k_mma, cudaFuncAttributeMaxDynamicSharedMemorySize, SMEM_SZ);

    k_prep_e <<<Kv / 32, 256>>>(emb);
    k_split_x<<<dim3(Tv / 64, Dv / 64, Bv), 256>>>(z);
    k_mma    <<<Nv / 64, 256, SMEM_SZ>>>();
    k_rescore<<<256, 256>>>();
    k_fix    <<<16, 256>>>();
    k_post   <<<Nv / 32, 256>>>(emb, out);
    k_final  <<<1, 256>>>(out, out_size);
}

// round 15
// speedup vs baseline: 1.8393x; 1.3058x over previous
#include <cuda_runtime.h>
#include <cuda_fp16.h>
#include <cstdint>
#include <math.h>

// VectorQuantizer: z_e (16,256,1024) f32, emb (8192,256) f32
// out = [ quantized (16,256,1024), vq_loss, perplexity ]  (f32)

#define Bv 16
#define Dv 256
#define Tv 1024
#define Kv 8192
#define Nv 16384
#define BDT (Bv*Dv*Tv)

// fp16 1-term (xhi*ehi): pairwise comparison error std ~9e-3; TAU=0.05 ~ 5.5 sigma
#define TAU 0.05f

// ---------------- device scratch ----------------
__device__ __align__(16) __half g_xhi[(size_t)Nv * Dv];
__device__ __align__(16) float  g_xf [(size_t)Nv * Dv];
__device__ __align__(16) __half g_ehi[(size_t)Kv * Dv];
__device__ __align__(16) float g_eT[(size_t)Dv * Kv];   // transposed codebook (f32)
__device__ __align__(16) float g_h[Kv];
__device__ __align__(16) float g_xsq[Nv];
__device__ __align__(16) float g_m[Nv];
__device__ __align__(16) int   g_idx[Nv];
__device__ __align__(16) float g_cnt[Kv];
__device__ int g_nflag;
__device__ __align__(16) int g_flags[Nv];
__device__ __align__(16) unsigned long long g_key[Nv];
__device__ double g_ps[64], g_pe[64];

// ---------------- helpers ----------------
__device__ __forceinline__ uint32_t smem_u32(const void* p) {
    uint32_t a;
    asm("{ .reg .u64 t; cvta.to.shared.u64 t, %1; cvt.u32.u64 %0, t; }" : "=r"(a) : "l"(p));
    return a;
}
#define SW(o) ((o) ^ ((((uint32_t)(o)) >> 3) & 0x70u))

#define LDMX4(r, a) \
    asm volatile("ldmatrix.sync.aligned.m8n8.x4.shared.b16 {%0,%1,%2,%3}, [%4];" \
        : "=r"((r)[0]), "=r"((r)[1]), "=r"((r)[2]), "=r"((r)[3]) : "r"(a))

#define MMA16816(c, a, b0, b1) \
    asm volatile("mma.sync.aligned.m16n8k16.row.col.f32.f16.f16.f32 " \
        "{%0,%1,%2,%3}, {%4,%5,%6,%7}, {%8,%9}, {%0,%1,%2,%3};" \
        : "+f"((c)[0]), "+f"((c)[1]), "+f"((c)[2]), "+f"((c)[3]) \
        : "r"((a)[0]), "r"((a)[1]), "r"((a)[2]), "r"((a)[3]), "r"(b0), "r"(b1))

#define CP16(dst, src) \
    asm volatile("cp.async.cg.shared.global [%0], [%1], 16;" :: "r"(dst), "l"(src))
#define CP_COMMIT() asm volatile("cp.async.commit_group;" ::: "memory")
#define CP_WAIT0()  asm volatile("cp.async.wait_group 0;" ::: "memory")

// monotonic float -> uint map (order preserving)
__device__ __forceinline__ uint32_t fmono(float f) {
    uint32_t u = __float_as_uint(f);
    return (u & 0x80000000u) ? ~u : (u | 0x80000000u);
}

// ---------------- fused prep: blocks [0,256) = emb prep; [256,1280) = z transpose ----------------
__global__ void k_prep(const float* __restrict__ emb, const float* __restrict__ z) {
    __shared__ float sm[32 * 257];
    int tid = threadIdx.x;
    if (blockIdx.x < 256) {
        // emb -> ehi + eT + half norms + zero cnt/flag (one read)
        float (*tile)[257] = (float(*)[257])sm;
        int k0 = blockIdx.x * 32;
        for (int i = tid; i < 32 * Dv; i += 256) {
            int r = i >> 8, d = i & 255;
            tile[r][d] = emb[(size_t)(k0 + r) * Dv + d];
        }
        __syncthreads();
        {
            int c = tid >> 3, p = tid & 7;
            const float* row = &tile[c][p * 32];
            float s = 0.f;
#pragma unroll
            for (int d = 0; d < 32; d++) s += row[d] * row[d];
#pragma unroll
            for (int o = 4; o; o >>= 1) s += __shfl_xor_sync(0xffffffffu, s, o);
            if (p == 0) {
                g_h[k0 + c] = 0.5f * s;
                g_cnt[k0 + c] = 0.f;
            }
        }
        if (blockIdx.x == 0 && tid == 0) g_nflag = 0;
        for (int i = tid; i < 32 * 128; i += 256) {
            int r = i >> 7, d2 = i & 127;
            __half2 h2 = __floats2half2_rn(tile[r][d2 * 2], tile[r][d2 * 2 + 1]);
            ((__half2*)g_ehi)[(size_t)(k0 + r) * (Dv / 2) + d2] = h2;
        }
        {
            int tx = tid & 31, ty = tid >> 5;
#pragma unroll 4
            for (int j = 0; j < 32; j++) {
                int d = ty * 32 + j;
                g_eT[(size_t)d * Kv + k0 + tx] = tile[tx][d];
            }
        }
    } else {
        // transpose z -> x[n][d] f32 + fp16 hi
        float (*tile)[65] = (float(*)[65])sm;
        int idx = blockIdx.x - 256;
        int t0 = (idx & 15) * 64, d0 = ((idx >> 4) & 3) * 64, b = idx >> 6;
        const float* src = z + ((size_t)b * Dv + d0) * Tv + t0;
        for (int i = tid; i < 1024; i += 256) {
            int dd = i >> 4, tq = i & 15;
            float4 v = *(const float4*)(src + (size_t)dd * Tv + tq * 4);
            tile[dd][tq * 4 + 0] = v.x; tile[dd][tq * 4 + 1] = v.y;
            tile[dd][tq * 4 + 2] = v.z; tile[dd][tq * 4 + 3] = v.w;
        }
        __syncthreads();
        int n0 = b * Tv + t0;
        for (int i = tid; i < 1024; i += 256) {
            int tt = i >> 4, dq = i & 15;
            float y[4];
#pragma unroll
            for (int c = 0; c < 4; c++) y[c] = tile[dq * 4 + c][tt];
            size_t o = (size_t)(n0 + tt) * Dv + d0 + dq * 4;
            *(float4*)(g_xf + o) = make_float4(y[0], y[1], y[2], y[3]);
            __half hi[4];
#pragma unroll
            for (int c = 0; c < 4; c++) hi[c] = __float2half_rn(y[c]);
            *(uint2*)(g_xhi + o) = *(uint2*)hi;
        }
    }
}

// ---------------- main: 64-row CTAs, 2 CTAs/SM, fp16 1-term GEMM + fused argmax ----------------
// Warp w: row-group rg=w>>2 (rows rg*32..+31), col-group cg=w&3 (cols cg*32..+31).
// smem: A [0,32K): 4 d-blocks x [64r][64d] SW128 (8KB each);
//       B double buffer [32K,96K): 2 x 32KB chunks ([128 codes][128d] = 2 d-blocks) via cp.async.
#define SM_B   32768
#define SMEM_SZ (98304 + 2048)

__global__ __launch_bounds__(256, 2) void k_mma() {
    extern __shared__ char smraw[];
    uint32_t raw = smem_u32(smraw);
    uint32_t sb = (raw + 1023u) & ~1023u;
    char* smp = smraw + (sb - raw);
    const int tid = threadIdx.x, wid = tid >> 5, lane = tid & 31;
    const int n0 = blockIdx.x * 64;
    const int rg = wid >> 2, cg = wid & 3;
    const int g = lane >> 2, tg = lane & 3;

    // stage A: Xhi, 4 d-blocks of [64r][64 fp16] SW128 (2048 16B units)
    for (int u = tid; u < 2048; u += 256) {
        int c = u >> 9, r = (u >> 3) & 63, q = u & 7;
        size_t so = (size_t)(n0 + r) * Dv + c * 64 + q * 8;
        *(uint4*)(smp + c * 8192 + SW(r * 128 + q * 16)) = *(const uint4*)(g_xhi + so);
    }

    const int m = lane >> 3, j7 = lane & 7;
    uint32_t arow[2];
#pragma unroll
    for (int s = 0; s < 2; s++)
        arow[s] = (uint32_t)(rg * 32 + s * 16 + (m & 1) * 8 + j7) * 128;
    const uint32_t ach   = (uint32_t)(lane >> 4) * 16;
    const uint32_t bbase = (uint32_t)(cg * 32 + (m >> 1) * 8 + j7) * 128 + (uint32_t)(m & 1) * 16;

    // cp.async 32KB chunk loader: chunk gidx = kt*2 + h -> buf gidx&1
    // chunk covers [128 codes][128 d] = d-blocks {2h, 2h+1}, stored as 2 x 16KB sub-tiles
    auto load_chunk = [&](int gidx) {
        int kt = gidx >> 1, h = gidx & 1;
        uint32_t bb = sb + SM_B + (gidx & 1 ? 32768 : 0);
        const __half* sh = g_ehi + (size_t)(kt * 128) * Dv + h * 128;
#pragma unroll
        for (int j = 0; j < 8; j++) {
            int u = tid + 256 * j;             // 0..2047 16B units
            int db = u >> 10, r = (u >> 3) & 127, q = u & 7;
            CP16(bb + db * 16384 + SW(r * 128 + q * 16),
                 sh + (size_t)r * Dv + db * 64 + q * 8);
        }
    };

    load_chunk(0);
    CP_COMMIT();
    CP_WAIT0();
    __syncthreads();

    // trackers: 4 rows per thread: r = s*2+half -> row rg*32 + s*16 + g + half*8
    float best[4]  = { -3.4e38f, -3.4e38f, -3.4e38f, -3.4e38f };
    float best2[4] = { -3.4e38f, -3.4e38f, -3.4e38f, -3.4e38f };
    int   bk[4]    = { 0, 0, 0, 0 };

    uint32_t A[2][2][4];   // [buf][stripe][4]
    uint32_t Bf[2][2][4];  // [buf][ntile][4]

#pragma unroll 1
    for (int kt = 0; kt < 64; kt++) {
        float acc[8][4];
#pragma unroll
        for (int i = 0; i < 8; i++)
#pragma unroll
            for (int q = 0; q < 4; q++) acc[i][q] = 0.f;

#pragma unroll 1
        for (int c2 = 0; c2 < 2; c2++) {
            int gi = kt * 2 + c2;
            if (gi < 127) { load_chunk(gi + 1); CP_COMMIT(); }

            const uint32_t bbuf = sb + SM_B + (gi & 1 ? 32768 : 0);
#pragma unroll
            for (int cc = 0; cc < 2; cc++) {
                const int c = c2 * 2 + cc;
                const uint32_t abase = sb + c * 8192;
                const uint32_t bB = bbuf + cc * 16384;

                // preload ds=0 fragments
#pragma unroll
                for (int s = 0; s < 2; s++)
                    LDMX4(A[0][s], abase + SW(arow[s] + ach));
#pragma unroll
                for (int nt = 0; nt < 2; nt++)
                    LDMX4(Bf[0][nt], bB + SW(bbase + nt * 2048));

#pragma unroll
                for (int ds = 0; ds < 4; ds++) {
                    const int ab = ds & 1;
                    // prefetch ds+1 fragments while issuing ds MMAs
                    if (ds < 3) {
#pragma unroll
                        for (int s = 0; s < 2; s++)
                            LDMX4(A[ab ^ 1][s], abase + SW(arow[s] + (ds + 1) * 32 + ach));
#pragma unroll
                        for (int nt = 0; nt < 2; nt++)
                            LDMX4(Bf[ab ^ 1][nt], bB + SW(bbase + nt * 2048 + (ds + 1) * 32));
                    }
                    // 8 MMAs
#pragma unroll
                    for (int s = 0; s < 2; s++)
#pragma unroll
                        for (int nt = 0; nt < 2; nt++) {
                            MMA16816(acc[s * 4 + nt * 2],     A[ab][s], Bf[ab][nt][0], Bf[ab][nt][1]);
                            MMA16816(acc[s * 4 + nt * 2 + 1], A[ab][s], Bf[ab][nt][2], Bf[ab][nt][3]);
                        }
                }
            }
            if (gi < 127) CP_WAIT0();
            __syncthreads();
        }

        // epilogue: fold this 128-col tile (32 cols for this warp) into trackers
#pragma unroll
        for (int s = 0; s < 2; s++)
#pragma unroll
            for (int nt = 0; nt < 2; nt++)
#pragma unroll
                for (int j = 0; j < 2; j++) {
                    int t = s * 4 + nt * 2 + j;
                    int col = kt * 128 + cg * 32 + nt * 16 + j * 8 + 2 * tg;
                    float h0 = __ldg(g_h + col), h1 = __ldg(g_h + col + 1);
                    int r0 = s * 2, r1 = s * 2 + 1;
                    float v00 = acc[t][0] - h0, v01 = acc[t][1] - h1;
                    float v10 = acc[t][2] - h0, v11 = acc[t][3] - h1;
                    if (v00 > best[r0]) { best2[r0] = best[r0]; best[r0] = v00; bk[r0] = col; }
                    else if (v00 > best2[r0]) best2[r0] = v00;
                    if (v01 > best[r0]) { best2[r0] = best[r0]; best[r0] = v01; bk[r0] = col + 1; }
                    else if (v01 > best2[r0]) best2[r0] = v01;
                    if (v10 > best[r1]) { best2[r1] = best[r1]; best[r1] = v10; bk[r1] = col; }
                    else if (v10 > best2[r1]) best2[r1] = v10;
                    if (v11 > best[r1]) { best2[r1] = best[r1]; best[r1] = v11; bk[r1] = col + 1; }
                    else if (v11 > best2[r1]) best2[r1] = v11;
                }
    }

    // reduce across the 4 lanes (tg) sharing each row
#pragma unroll
    for (int r = 0; r < 4; r++) {
#pragma unroll
        for (int o = 1; o <= 2; o <<= 1) {
            float ob = __shfl_xor_sync(0xffffffffu, best[r], o);
            float os = __shfl_xor_sync(0xffffffffu, best2[r], o);
            int   ok = __shfl_xor_sync(0xffffffffu, bk[r], o);
            if (ob > best[r] || (ob == best[r] && ok < bk[r])) {
                best2[r] = fmaxf(best[r], os);
                best[r] = ob; bk[r] = ok;
            } else {
                best2[r] = fmaxf(best2[r], ob);
            }
        }
    }

    // cross-warp (col-group) merge via smem: fb/fs/fk [4][64]
    __syncthreads();
    float* fb = (float*)smp;
    float* fs = fb + 256;
    int*   fk = (int*)(fs + 256);
    if (tg == 0) {
#pragma unroll
        for (int r = 0; r < 4; r++) {
            int row = rg * 32 + (r >> 1) * 16 + g + (r & 1) * 8;
            fb[cg * 64 + row] = best[r];
            fs[cg * 64 + row] = best2[r];
            fk[cg * 64 + row] = bk[r];
        }
    }
    __syncthreads();
    if (tid < 64) {
        float bb = fb[tid], ss = fs[tid];
        int kk = fk[tid];
#pragma unroll
        for (int c2 = 1; c2 < 4; c2++) {
            float ob = fb[c2 * 64 + tid], os = fs[c2 * 64 + tid];
            int ok = fk[c2 * 64 + tid];
            if (ob > bb || (ob == bb && ok < kk)) { ss = fmaxf(bb, os); bb = ob; kk = ok; }
            else ss = fmaxf(ss, ob);
        }
        int n = n0 + tid;
        g_idx[n] = kk;
        if (bb - ss < TAU) {
            g_key[n] = 0ull;
            int pos = atomicAdd(&g_nflag, 1);
            g_flags[pos] = n;
        }
    }
}

// ---------------- rescore: (16-row batch) x (K/16 slice = 512 codes) per work item ----------------
#define RB 16
__global__ __launch_bounds__(256, 2) void k_rescore() {
    __shared__ float sx[RB][Dv];
    __shared__ int   sn[RB];
    __shared__ unsigned long long wm[8];
    int tid = threadIdx.x, wid = tid >> 5, lane = tid & 31;
    int nf = g_nflag; if (nf > Nv) nf = Nv;
    if (nf <= 0) return;
    int nbatch = (nf + RB - 1) / RB;
    int nwork = nbatch * 16;
    for (int w = blockIdx.x; w < nwork; w += gridDim.x) {
        int bi = w >> 4, ks = w & 15;
        int r0 = bi * RB;
        int nr = nf - r0; if (nr > RB) nr = RB;
        if (tid < RB) sn[tid] = g_flags[r0 + (tid < nr ? tid : 0)];
        __syncthreads();
        for (int i = tid; i < RB * (Dv / 4); i += 256) {
            int r = i >> 6, d = i & 63;
            *(float4*)&sx[r][d * 4] = *(const float4*)(g_xf + (size_t)sn[r] * Dv + d * 4);
        }
        __syncthreads();

        const int kA = ks * 512 + tid;
        const int kB = kA + 256;
        const float* epA = g_eT + kA;
        const float* epB = g_eT + kB;
        float sA[RB], sB[RB];
#pragma unroll
        for (int r = 0; r < RB; r++) { sA[r] = 0.f; sB[r] = 0.f; }

        float ea[2][4], eb[2][4];
#pragma unroll
        for (int c = 0; c < 4; c++) {
            ea[0][c] = epA[(size_t)c * Kv];
            eb[0][c] = epB[(size_t)c * Kv];
        }
#pragma unroll 2
        for (int d4 = 0; d4 < 64; d4++) {
            int pb = d4 & 1;
            if (d4 < 63) {
#pragma unroll
                for (int c = 0; c < 4; c++) {
                    ea[pb ^ 1][c] = epA[(size_t)((d4 + 1) * 4 + c) * Kv];
                    eb[pb ^ 1][c] = epB[(size_t)((d4 + 1) * 4 + c) * Kv];
                }
            }
#pragma unroll
            for (int r = 0; r < RB; r++) {
                float4 xv = *(const float4*)&sx[r][d4 * 4];
                sA[r] = fmaf(xv.x, ea[pb][0], fmaf(xv.y, ea[pb][1],
                          fmaf(xv.z, ea[pb][2], fmaf(xv.w, ea[pb][3], sA[r]))));
                sB[r] = fmaf(xv.x, eb[pb][0], fmaf(xv.y, eb[pb][1],
                          fmaf(xv.z, eb[pb][2], fmaf(xv.w, eb[pb][3], sB[r]))));
            }
        }

        float hA = g_h[kA], hB = g_h[kB];
#pragma unroll 1
        for (int r = 0; r < RB; r++) {
            if (r >= nr) break;
            float vA = sA[r] - hA, vB = sB[r] - hB;
            float v; int kk;
            if (vA >= vB) { v = vA; kk = kA; } else { v = vB; kk = kB; }
            unsigned long long key = ((unsigned long long)fmono(v) << 32)
                                   | (unsigned long long)(0xFFFFFFFFu - (uint32_t)kk);
#pragma unroll
            for (int o = 16; o; o >>= 1) {
                unsigned long long ok = __shfl_xor_sync(0xffffffffu, key, o);
                if (ok > key) key = ok;
            }
            if (lane == 0) wm[wid] = key;
            __syncthreads();
            if (tid == 0) {
                unsigned long long b = wm[0];
#pragma unroll
                for (int w2 = 1; w2 < 8; w2++) if (wm[w2] > b) b = wm[w2];
                atomicMax(&g_key[sn[r]], b);
            }
            __syncthreads();
        }
        __syncthreads();
    }
}

// ---------------- decode rescore keys into g_idx ----------------
__global__ void k_fix() {
    int nf = g_nflag; if (nf > Nv) nf = Nv;
    for (int f = blockIdx.x * 256 + threadIdx.x; f < nf; f += gridDim.x * 256) {
        int n = g_flags[f];
        unsigned long long key = g_key[n];
        g_idx[n] = (int)(0xFFFFFFFFu - (uint32_t)(key & 0xFFFFFFFFull));
    }
}

// ---------------- post: exact g_m/xsq + histogram + scatter (one emb gather) ----------------
__global__ void k_post(const float* __restrict__ emb, float* __restrict__ out) {
    __shared__ float tile[32][257];
    __shared__ int sidx[32];
    int n0 = blockIdx.x * 32;
    int b = n0 >> 10, t0 = n0 & 1023;
    int tid = threadIdx.x;
    if (tid < 32) sidx[tid] = g_idx[n0 + tid];
    __syncthreads();
    for (int i = tid; i < 32 * Dv; i += 256) {
        int r = i >> 8, d = i & 255;
        tile[r][d] = emb[(size_t)sidx[r] * Dv + d];
    }
    __syncthreads();

    int w = tid >> 5, lane = tid & 31;
#pragma unroll 1
    for (int j = 0; j < 4; j++) {
        int r = w * 4 + j;
        int n = n0 + r;
        const float* x = g_xf + (size_t)n * Dv + lane * 8;
        float4 x0 = *(const float4*)(x), x1 = *(const float4*)(x + 4);
        const float* e = &tile[r][lane * 8];
        float s = x0.x * e[0] + x0.y * e[1] + x0.z * e[2] + x0.w * e[3]
                + x1.x * e[4] + x1.y * e[5] + x1.z * e[6] + x1.w * e[7];
        float q = x0.x * x0.x + x0.y * x0.y + x0.z * x0.z + x0.w * x0.w
                + x1.x * x1.x + x1.y * x1.y + x1.z * x1.z + x1.w * x1.w;
#pragma unroll
        for (int t = 16; t; t >>= 1) {
            s += __shfl_xor_sync(0xffffffffu, s, t);
            q += __shfl_xor_sync(0xffffffffu, q, t);
        }
        if (lane == 0) {
            g_m[n] = s - g_h[sidx[r]];
            g_xsq[n] = q;
            atomicAdd(&g_cnt[sidx[r]], 1.0f);
        }
    }

    // scatter transposed out (tile unchanged)
    float* ob = out + (size_t)b * Dv * Tv + t0;
    for (int i = tid; i < 32 * Dv; i += 256) {
        int d = i >> 5, r = i & 31;
        ob[(size_t)d * Tv + r] = tile[r][d];
    }
}

// ---------------- scalars: parallel partials + tiny finish ----------------
__global__ void k_final1() {
    __shared__ double sd[256];
    int tid = threadIdx.x, bid = blockIdx.x;
    int n = bid * 256 + tid;
    double s = (double)g_xsq[n] - 2.0 * (double)g_m[n];
    double e = 0.0;
    if (tid < 128) {
        int k = bid * 128 + tid;
        double p = (double)g_cnt[k] * (1.0 / (double)Nv);
        e = p * log(p + 1e-10);
    }
    sd[tid] = s; __syncthreads();
    for (int o = 128; o; o >>= 1) { if (tid < o) sd[tid] += sd[tid + o]; __syncthreads(); }
    if (tid == 0) g_ps[bid] = sd[0];
    __syncthreads();
    sd[tid] = e; __syncthreads();
    for (int o = 128; o; o >>= 1) { if (tid < o) sd[tid] += sd[tid + o]; __syncthreads(); }
    if (tid == 0) g_pe[bid] = sd[0];
}

__global__ void k_final2(float* __restrict__ out, int out_size) {
    if (threadIdx.x == 0 && out_size >= BDT + 2) {
        double s = 0.0, e = 0.0;
        for (int i = 0; i < 64; i++) { s += g_ps[i]; e += g_pe[i]; }
        out[BDT]     = (float)(0.25 * s / ((double)Nv * (double)Dv));
        out[BDT + 1] = (float)exp(-e);
    }
}

// ---------------- launch ----------------
extern "C" void kernel_launch(void* const* d_in, const int* in_sizes, int n_in,
                              void* d_out, int out_size) {
    const float* z   = (const float*)d_in[0];
    const float* emb = (const float*)d_in[1];
    float* out = (float*)d_out;

    cudaFuncSetAttribute(k_mma, cudaFuncAttributeMaxDynamicSharedMemorySize, SMEM_SZ);

    k_prep   <<<1280, 256>>>(emb, z);
    k_mma    <<<Nv / 64, 256, SMEM_SZ>>>();
    k_rescore<<<256, 256>>>();
    k_fix    <<<16, 256>>>();
    k_post   <<<Nv / 32, 256>>>(emb, out);
    k_final1 <<<64, 256>>>();
    k_final2 <<<1, 32>>>(out, out_size);
}

// round 16
// speedup vs baseline: 1.8534x; 1.0077x over previous
#include <cuda_runtime.h>
#include <cuda_fp16.h>
#include <cstdint>
#include <math.h>

// VectorQuantizer: z_e (16,256,1024) f32, emb (8192,256) f32
// out = [ quantized (16,256,1024), vq_loss, perplexity ]  (f32)

#define Bv 16
#define Dv 256
#define Tv 1024
#define Kv 8192
#define Nv 16384
#define BDT (Bv*Dv*Tv)

// fp16 1-term (xhi*ehi): pairwise comparison error std ~9e-3; TAU=0.05 ~ 5.5 sigma
#define TAU 0.05f

// ---------------- device scratch ----------------
__device__ __align__(16) __half g_xhi[(size_t)Nv * Dv];
__device__ __align__(16) float  g_xf [(size_t)Nv * Dv];
__device__ __align__(16) __half g_ehi[(size_t)Kv * Dv];
__device__ __align__(16) float g_eT[(size_t)Dv * Kv];   // transposed codebook (f32)
__device__ __align__(16) float g_h[Kv];
__device__ __align__(16) float g_xsq[Nv];
__device__ __align__(16) float g_m[Nv];
__device__ __align__(16) int   g_idx[Nv];
__device__ __align__(16) float g_cnt[Kv];
__device__ int g_nflag;
__device__ __align__(16) int g_flags[Nv];
__device__ __align__(16) unsigned long long g_key[Nv];
__device__ double g_ps[64], g_pe[64];

// ---------------- helpers ----------------
__device__ __forceinline__ uint32_t smem_u32(const void* p) {
    uint32_t a;
    asm("{ .reg .u64 t; cvta.to.shared.u64 t, %1; cvt.u32.u64 %0, t; }" : "=r"(a) : "l"(p));
    return a;
}
#define SW(o) ((o) ^ ((((uint32_t)(o)) >> 3) & 0x70u))

#define LDMX4(r, a) \
    asm volatile("ldmatrix.sync.aligned.m8n8.x4.shared.b16 {%0,%1,%2,%3}, [%4];" \
        : "=r"((r)[0]), "=r"((r)[1]), "=r"((r)[2]), "=r"((r)[3]) : "r"(a))

#define MMA16816(c, a, b0, b1) \
    asm volatile("mma.sync.aligned.m16n8k16.row.col.f32.f16.f16.f32 " \
        "{%0,%1,%2,%3}, {%4,%5,%6,%7}, {%8,%9}, {%0,%1,%2,%3};" \
        : "+f"((c)[0]), "+f"((c)[1]), "+f"((c)[2]), "+f"((c)[3]) \
        : "r"((a)[0]), "r"((a)[1]), "r"((a)[2]), "r"((a)[3]), "r"(b0), "r"(b1))

#define CP16(dst, src) \
    asm volatile("cp.async.cg.shared.global [%0], [%1], 16;" :: "r"(dst), "l"(src))
#define CP_COMMIT() asm volatile("cp.async.commit_group;" ::: "memory")
#define CP_WAIT0()  asm volatile("cp.async.wait_group 0;" ::: "memory")

// monotonic float -> uint map (order preserving; nonzero for all non-NaN inputs)
__device__ __forceinline__ uint32_t fmono(float f) {
    uint32_t u = __float_as_uint(f);
    return (u & 0x80000000u) ? ~u : (u | 0x80000000u);
}

// ---------------- fused prep: blocks [0,256) = emb prep; [256,1280) = z transpose ----------------
__global__ void k_prep(const float* __restrict__ emb, const float* __restrict__ z) {
    __shared__ float sm[32 * 257];
    int tid = threadIdx.x;
    if (blockIdx.x < 256) {
        // emb -> ehi + eT + half norms + zero cnt/flag/key (one read)
        float (*tile)[257] = (float(*)[257])sm;
        int k0 = blockIdx.x * 32;
        for (int i = tid; i < 32 * Dv; i += 256) {
            int r = i >> 8, d = i & 255;
            tile[r][d] = emb[(size_t)(k0 + r) * Dv + d];
        }
        if (tid < 64) g_key[blockIdx.x * 64 + tid] = 0ull;   // pre-zero keys (256*64 = Nv)
        __syncthreads();
        {
            int c = tid >> 3, p = tid & 7;
            const float* row = &tile[c][p * 32];
            float s = 0.f;
#pragma unroll
            for (int d = 0; d < 32; d++) s += row[d] * row[d];
#pragma unroll
            for (int o = 4; o; o >>= 1) s += __shfl_xor_sync(0xffffffffu, s, o);
            if (p == 0) {
                g_h[k0 + c] = 0.5f * s;
                g_cnt[k0 + c] = 0.f;
            }
        }
        if (blockIdx.x == 0 && tid == 0) g_nflag = 0;
        for (int i = tid; i < 32 * 128; i += 256) {
            int r = i >> 7, d2 = i & 127;
            __half2 h2 = __floats2half2_rn(tile[r][d2 * 2], tile[r][d2 * 2 + 1]);
            ((__half2*)g_ehi)[(size_t)(k0 + r) * (Dv / 2) + d2] = h2;
        }
        {
            int tx = tid & 31, ty = tid >> 5;
#pragma unroll 4
            for (int j = 0; j < 32; j++) {
                int d = ty * 32 + j;
                g_eT[(size_t)d * Kv + k0 + tx] = tile[tx][d];
            }
        }
    } else {
        // transpose z -> x[n][d] f32 + fp16 hi
        float (*tile)[65] = (float(*)[65])sm;
        int idx = blockIdx.x - 256;
        int t0 = (idx & 15) * 64, d0 = ((idx >> 4) & 3) * 64, b = idx >> 6;
        const float* src = z + ((size_t)b * Dv + d0) * Tv + t0;
        for (int i = tid; i < 1024; i += 256) {
            int dd = i >> 4, tq = i & 15;
            float4 v = *(const float4*)(src + (size_t)dd * Tv + tq * 4);
            tile[dd][tq * 4 + 0] = v.x; tile[dd][tq * 4 + 1] = v.y;
            tile[dd][tq * 4 + 2] = v.z; tile[dd][tq * 4 + 3] = v.w;
        }
        __syncthreads();
        int n0 = b * Tv + t0;
        for (int i = tid; i < 1024; i += 256) {
            int tt = i >> 4, dq = i & 15;
            float y[4];
#pragma unroll
            for (int c = 0; c < 4; c++) y[c] = tile[dq * 4 + c][tt];
            size_t o = (size_t)(n0 + tt) * Dv + d0 + dq * 4;
            *(float4*)(g_xf + o) = make_float4(y[0], y[1], y[2], y[3]);
            __half hi[4];
#pragma unroll
            for (int c = 0; c < 4; c++) hi[c] = __float2half_rn(y[c]);
            *(uint2*)(g_xhi + o) = *(uint2*)hi;
        }
    }
}

// ---------------- main: 64-row CTAs, 2 CTAs/SM, fp16 1-term GEMM + fused argmax ----------------
// Warp w: row-group rg=w>>2 (rows rg*32..+31), col-group cg=w&3 (cols cg*32..+31).
// smem: A [0,32K): 4 d-blocks x [64r][64d] SW128 (8KB each);
//       B double buffer [32K,96K): 2 x 32KB chunks ([128 codes][128d] = 2 d-blocks) via cp.async.
#define SM_B   32768
#define SMEM_SZ (98304 + 2048)

__global__ __launch_bounds__(256, 2) void k_mma() {
    extern __shared__ char smraw[];
    uint32_t raw = smem_u32(smraw);
    uint32_t sb = (raw + 1023u) & ~1023u;
    char* smp = smraw + (sb - raw);
    const int tid = threadIdx.x, wid = tid >> 5, lane = tid & 31;
    const int n0 = blockIdx.x * 64;
    const int rg = wid >> 2, cg = wid & 3;
    const int g = lane >> 2, tg = lane & 3;

    // stage A: Xhi, 4 d-blocks of [64r][64 fp16] SW128 (2048 16B units)
    for (int u = tid; u < 2048; u += 256) {
        int c = u >> 9, r = (u >> 3) & 63, q = u & 7;
        size_t so = (size_t)(n0 + r) * Dv + c * 64 + q * 8;
        *(uint4*)(smp + c * 8192 + SW(r * 128 + q * 16)) = *(const uint4*)(g_xhi + so);
    }

    const int m = lane >> 3, j7 = lane & 7;
    uint32_t arow[2];
#pragma unroll
    for (int s = 0; s < 2; s++)
        arow[s] = (uint32_t)(rg * 32 + s * 16 + (m & 1) * 8 + j7) * 128;
    const uint32_t ach   = (uint32_t)(lane >> 4) * 16;
    const uint32_t bbase = (uint32_t)(cg * 32 + (m >> 1) * 8 + j7) * 128 + (uint32_t)(m & 1) * 16;

    // cp.async 32KB chunk loader: chunk gidx = kt*2 + h -> buf gidx&1
    auto load_chunk = [&](int gidx) {
        int kt = gidx >> 1, h = gidx & 1;
        uint32_t bb = sb + SM_B + (gidx & 1 ? 32768 : 0);
        const __half* sh = g_ehi + (size_t)(kt * 128) * Dv + h * 128;
#pragma unroll
        for (int j = 0; j < 8; j++) {
            int u = tid + 256 * j;             // 0..2047 16B units
            int db = u >> 10, r = (u >> 3) & 127, q = u & 7;
            CP16(bb + db * 16384 + SW(r * 128 + q * 16),
                 sh + (size_t)r * Dv + db * 64 + q * 8);
        }
    };

    load_chunk(0);
    CP_COMMIT();
    CP_WAIT0();
    __syncthreads();

    // trackers: 4 rows per thread: r = s*2+half -> row rg*32 + s*16 + g + half*8
    float best[4]  = { -3.4e38f, -3.4e38f, -3.4e38f, -3.4e38f };
    float best2[4] = { -3.4e38f, -3.4e38f, -3.4e38f, -3.4e38f };
    int   bk[4]    = { 0, 0, 0, 0 };

    uint32_t A[2][2][4];   // [buf][stripe][4]
    uint32_t Bf[2][2][4];  // [buf][ntile][4]

#pragma unroll 1
    for (int kt = 0; kt < 64; kt++) {
        float acc[8][4];
#pragma unroll
        for (int i = 0; i < 8; i++)
#pragma unroll
            for (int q = 0; q < 4; q++) acc[i][q] = 0.f;

#pragma unroll 1
        for (int c2 = 0; c2 < 2; c2++) {
            int gi = kt * 2 + c2;
            if (gi < 127) { load_chunk(gi + 1); CP_COMMIT(); }

            const uint32_t bbuf = sb + SM_B + (gi & 1 ? 32768 : 0);
#pragma unroll
            for (int cc = 0; cc < 2; cc++) {
                const int c = c2 * 2 + cc;
                const uint32_t abase = sb + c * 8192;
                const uint32_t bB = bbuf + cc * 16384;

                // preload ds=0 fragments
#pragma unroll
                for (int s = 0; s < 2; s++)
                    LDMX4(A[0][s], abase + SW(arow[s] + ach));
#pragma unroll
                for (int nt = 0; nt < 2; nt++)
                    LDMX4(Bf[0][nt], bB + SW(bbase + nt * 2048));

#pragma unroll
                for (int ds = 0; ds < 4; ds++) {
                    const int ab = ds & 1;
                    // prefetch ds+1 fragments while issuing ds MMAs
                    if (ds < 3) {
#pragma unroll
                        for (int s = 0; s < 2; s++)
                            LDMX4(A[ab ^ 1][s], abase + SW(arow[s] + (ds + 1) * 32 + ach));
#pragma unroll
                        for (int nt = 0; nt < 2; nt++)
                            LDMX4(Bf[ab ^ 1][nt], bB + SW(bbase + nt * 2048 + (ds + 1) * 32));
                    }
                    // 8 MMAs
#pragma unroll
                    for (int s = 0; s < 2; s++)
#pragma unroll
                        for (int nt = 0; nt < 2; nt++) {
                            MMA16816(acc[s * 4 + nt * 2],     A[ab][s], Bf[ab][nt][0], Bf[ab][nt][1]);
                            MMA16816(acc[s * 4 + nt * 2 + 1], A[ab][s], Bf[ab][nt][2], Bf[ab][nt][3]);
                        }
                }
            }
            if (gi < 127) CP_WAIT0();
            __syncthreads();
        }

        // epilogue: fold this 128-col tile (32 cols for this warp) into trackers
#pragma unroll
        for (int s = 0; s < 2; s++)
#pragma unroll
            for (int nt = 0; nt < 2; nt++)
#pragma unroll
                for (int j = 0; j < 2; j++) {
                    int t = s * 4 + nt * 2 + j;
                    int col = kt * 128 + cg * 32 + nt * 16 + j * 8 + 2 * tg;
                    float h0 = __ldg(g_h + col), h1 = __ldg(g_h + col + 1);
                    int r0 = s * 2, r1 = s * 2 + 1;
                    float v00 = acc[t][0] - h0, v01 = acc[t][1] - h1;
                    float v10 = acc[t][2] - h0, v11 = acc[t][3] - h1;
                    if (v00 > best[r0]) { best2[r0] = best[r0]; best[r0] = v00; bk[r0] = col; }
                    else if (v00 > best2[r0]) best2[r0] = v00;
                    if (v01 > best[r0]) { best2[r0] = best[r0]; best[r0] = v01; bk[r0] = col + 1; }
                    else if (v01 > best2[r0]) best2[r0] = v01;
                    if (v10 > best[r1]) { best2[r1] = best[r1]; best[r1] = v10; bk[r1] = col; }
                    else if (v10 > best2[r1]) best2[r1] = v10;
                    if (v11 > best[r1]) { best2[r1] = best[r1]; best[r1] = v11; bk[r1] = col + 1; }
                    else if (v11 > best2[r1]) best2[r1] = v11;
                }
    }

    // reduce across the 4 lanes (tg) sharing each row
#pragma unroll
    for (int r = 0; r < 4; r++) {
#pragma unroll
        for (int o = 1; o <= 2; o <<= 1) {
            float ob = __shfl_xor_sync(0xffffffffu, best[r], o);
            float os = __shfl_xor_sync(0xffffffffu, best2[r], o);
            int   ok = __shfl_xor_sync(0xffffffffu, bk[r], o);
            if (ob > best[r] || (ob == best[r] && ok < bk[r])) {
                best2[r] = fmaxf(best[r], os);
                best[r] = ob; bk[r] = ok;
            } else {
                best2[r] = fmaxf(best2[r], ob);
            }
        }
    }

    // cross-warp (col-group) merge via smem: fb/fs/fk [4][64]
    __syncthreads();
    float* fb = (float*)smp;
    float* fs = fb + 256;
    int*   fk = (int*)(fs + 256);
    if (tg == 0) {
#pragma unroll
        for (int r = 0; r < 4; r++) {
            int row = rg * 32 + (r >> 1) * 16 + g + (r & 1) * 8;
            fb[cg * 64 + row] = best[r];
            fs[cg * 64 + row] = best2[r];
            fk[cg * 64 + row] = bk[r];
        }
    }
    __syncthreads();
    if (tid < 64) {
        float bb = fb[tid], ss = fs[tid];
        int kk = fk[tid];
#pragma unroll
        for (int c2 = 1; c2 < 4; c2++) {
            float ob = fb[c2 * 64 + tid], os = fs[c2 * 64 + tid];
            int ok = fk[c2 * 64 + tid];
            if (ob > bb || (ob == bb && ok < kk)) { ss = fmaxf(bb, os); bb = ob; kk = ok; }
            else ss = fmaxf(ss, ob);
        }
        int n = n0 + tid;
        g_idx[n] = kk;
        if (bb - ss < TAU) {
            int pos = atomicAdd(&g_nflag, 1);
            g_flags[pos] = n;
        }
    }
}

// ---------------- rescore: (16-row batch) x (K/16 slice = 512 codes) per work item ----------------
#define RB 16
__global__ __launch_bounds__(256, 2) void k_rescore() {
    __shared__ float sx[RB][Dv];
    __shared__ int   sn[RB];
    int tid = threadIdx.x, lane = tid & 31;
    int nf = g_nflag; if (nf > Nv) nf = Nv;
    if (nf <= 0) return;
    int nbatch = (nf + RB - 1) / RB;
    int nwork = nbatch * 16;
    for (int w = blockIdx.x; w < nwork; w += gridDim.x) {
        int bi = w >> 4, ks = w & 15;
        int r0 = bi * RB;
        int nr = nf - r0; if (nr > RB) nr = RB;
        if (tid < RB) sn[tid] = g_flags[r0 + (tid < nr ? tid : 0)];
        __syncthreads();
        for (int i = tid; i < RB * (Dv / 4); i += 256) {
            int r = i >> 6, d = i & 63;
            *(float4*)&sx[r][d * 4] = *(const float4*)(g_xf + (size_t)sn[r] * Dv + d * 4);
        }
        __syncthreads();

        const int kA = ks * 512 + tid;
        const int kB = kA + 256;
        const float* epA = g_eT + kA;
        const float* epB = g_eT + kB;
        float sA[RB], sB[RB];
#pragma unroll
        for (int r = 0; r < RB; r++) { sA[r] = 0.f; sB[r] = 0.f; }

        float ea[2][4], eb[2][4];
#pragma unroll
        for (int c = 0; c < 4; c++) {
            ea[0][c] = epA[(size_t)c * Kv];
            eb[0][c] = epB[(size_t)c * Kv];
        }
#pragma unroll 2
        for (int d4 = 0; d4 < 64; d4++) {
            int pb = d4 & 1;
            if (d4 < 63) {
#pragma unroll
                for (int c = 0; c < 4; c++) {
                    ea[pb ^ 1][c] = epA[(size_t)((d4 + 1) * 4 + c) * Kv];
                    eb[pb ^ 1][c] = epB[(size_t)((d4 + 1) * 4 + c) * Kv];
                }
            }
#pragma unroll
            for (int r = 0; r < RB; r++) {
                float4 xv = *(const float4*)&sx[r][d4 * 4];
                sA[r] = fmaf(xv.x, ea[pb][0], fmaf(xv.y, ea[pb][1],
                          fmaf(xv.z, ea[pb][2], fmaf(xv.w, ea[pb][3], sA[r]))));
                sB[r] = fmaf(xv.x, eb[pb][0], fmaf(xv.y, eb[pb][1],
                          fmaf(xv.z, eb[pb][2], fmaf(xv.w, eb[pb][3], sB[r]))));
            }
        }

        float hA = g_h[kA], hB = g_h[kB];
#pragma unroll 1
        for (int r = 0; r < RB; r++) {
            if (r >= nr) break;
            float vA = sA[r] - hA, vB = sB[r] - hB;
            float v; int kk;
            if (vA >= vB) { v = vA; kk = kA; } else { v = vB; kk = kB; }
            unsigned long long key = ((unsigned long long)fmono(v) << 32)
                                   | (unsigned long long)(0xFFFFFFFFu - (uint32_t)kk);
#pragma unroll
            for (int o = 16; o; o >>= 1) {
                unsigned long long ok = __shfl_xor_sync(0xffffffffu, key, o);
                if (ok > key) key = ok;
            }
            if (lane == 0) atomicMax(&g_key[sn[r]], key);   // warp-direct merge (no barriers)
        }
        __syncthreads();   // protect sx/sn before next work item
    }
}

// ---------------- post: decode keys + exact g_m/xsq + histogram + scatter ----------------
__global__ void k_post(const float* __restrict__ emb, float* __restrict__ out) {
    __shared__ float tile[32][257];
    __shared__ int sidx[32];
    int n0 = blockIdx.x * 32;
    int b = n0 >> 10, t0 = n0 & 1023;
    int tid = threadIdx.x;
    if (tid < 32) {
        int n = n0 + tid;
        unsigned long long key = g_key[n];
        sidx[tid] = key ? (int)(0xFFFFFFFFu - (uint32_t)(key & 0xFFFFFFFFull))
                        : g_idx[n];
    }
    __syncthreads();
    for (int i = tid; i < 32 * Dv; i += 256) {
        int r = i >> 8, d = i & 255;
        tile[r][d] = emb[(size_t)sidx[r] * Dv + d];
    }
    __syncthreads();

    int w = tid >> 5, lane = tid & 31;
#pragma unroll 1
    for (int j = 0; j < 4; j++) {
        int r = w * 4 + j;
        int n = n0 + r;
        const float* x = g_xf + (size_t)n * Dv + lane * 8;
        float4 x0 = *(const float4*)(x), x1 = *(const float4*)(x + 4);
        const float* e = &tile[r][lane * 8];
        float s = x0.x * e[0] + x0.y * e[1] + x0.z * e[2] + x0.w * e[3]
                + x1.x * e[4] + x1.y * e[5] + x1.z * e[6] + x1.w * e[7];
        float q = x0.x * x0.x + x0.y * x0.y + x0.z * x0.z + x0.w * x0.w
                + x1.x * x1.x + x1.y * x1.y + x1.z * x1.z + x1.w * x1.w;
#pragma unroll
        for (int t = 16; t; t >>= 1) {
            s += __shfl_xor_sync(0xffffffffu, s, t);
            q += __shfl_xor_sync(0xffffffffu, q, t);
        }
        if (lane == 0) {
            g_m[n] = s - g_h[sidx[r]];
            g_xsq[n] = q;
            atomicAdd(&g_cnt[sidx[r]], 1.0f);
        }
    }

    // scatter transposed out (tile unchanged)
    float* ob = out + (size_t)b * Dv * Tv + t0;
    for (int i = tid; i < 32 * Dv; i += 256) {
        int d = i >> 5, r = i & 31;
        ob[(size_t)d * Tv + r] = tile[r][d];
    }
}

// ---------------- scalars: parallel partials + tiny finish ----------------
__global__ void k_final1() {
    __shared__ double sd[256];
    int tid = threadIdx.x, bid = blockIdx.x;
    int n = bid * 256 + tid;
    double s = (double)g_xsq[n] - 2.0 * (double)g_m[n];
    double e = 0.0;
    if (tid < 128) {
        int k = bid * 128 + tid;
        double p = (double)g_cnt[k] * (1.0 / (double)Nv);
        e = p * log(p + 1e-10);
    }
    sd[tid] = s; __syncthreads();
    for (int o = 128; o; o >>= 1) { if (tid < o) sd[tid] += sd[tid + o]; __syncthreads(); }
    if (tid == 0) g_ps[bid] = sd[0];
    __syncthreads();
    sd[tid] = e; __syncthreads();
    for (int o = 128; o; o >>= 1) { if (tid < o) sd[tid] += sd[tid + o]; __syncthreads(); }
    if (tid == 0) g_pe[bid] = sd[0];
}

__global__ void k_final2(float* __restrict__ out, int out_size) {
    if (threadIdx.x == 0 && out_size >= BDT + 2) {
        double s = 0.0, e = 0.0;
        for (int i = 0; i < 64; i++) { s += g_ps[i]; e += g_pe[i]; }
        out[BDT]     = (float)(0.25 * s / ((double)Nv * (double)Dv));
        out[BDT + 1] = (float)exp(-e);
    }
}

// ---------------- launch ----------------
extern "C" void kernel_launch(void* const* d_in, const int* in_sizes, int n_in,
                              void* d_out, int out_size) {
    const float* z   = (const float*)d_in[0];
    const float* emb = (const float*)d_in[1];
    float* out = (float*)d_out;

    cudaFuncSetAttribute(k_mma, cudaFuncAttributeMaxDynamicSharedMemorySize, SMEM_SZ);

    k_prep   <<<1280, 256>>>(emb, z);
    k_mma    <<<Nv / 64, 256, SMEM_SZ>>>();
    k_rescore<<<256, 256>>>();
    k_post   <<<Nv / 32, 256>>>(emb, out);
    k_final1 <<<64, 256>>>();
    k_final2 <<<1, 32>>>(out, out_size);
}

// round 17
// speedup vs baseline: 1.8619x; 1.0046x over previous
#include <cuda_runtime.h>
#include <cuda_fp16.h>
#include <cstdint>
#include <math.h>

// VectorQuantizer: z_e (16,256,1024) f32, emb (8192,256) f32
// out = [ quantized (16,256,1024), vq_loss, perplexity ]  (f32)

#define Bv 16
#define Dv 256
#define Tv 1024
#define Kv 8192
#define Nv 16384
#define BDT (Bv*Dv*Tv)

// fp16 1-term (xhi*ehi): pairwise comparison error std ~9e-3; TAU=0.05 ~ 5.5 sigma
#define TAU 0.05f

// ---------------- device scratch ----------------
__device__ __align__(16) __half g_xhi[(size_t)Nv * Dv];
__device__ __align__(16) float  g_xf [(size_t)Nv * Dv];
__device__ __align__(16) __half g_ehi[(size_t)Kv * Dv];
__device__ __align__(16) float g_eT[(size_t)Dv * Kv];   // transposed codebook (f32)
__device__ __align__(16) float g_h[Kv];
__device__ __align__(16) float g_xsq[Nv];
__device__ __align__(16) float g_m[Nv];
__device__ __align__(16) int   g_idx[Nv];
__device__ __align__(16) float g_cnt[Kv];
__device__ int g_nflag;
__device__ __align__(16) int g_flags[Nv];
__device__ __align__(16) unsigned long long g_key[Nv];
__device__ double g_ps[64], g_pe[64];

// ---------------- helpers ----------------
__device__ __forceinline__ uint32_t smem_u32(const void* p) {
    uint32_t a;
    asm("{ .reg .u64 t; cvta.to.shared.u64 t, %1; cvt.u32.u64 %0, t; }" : "=r"(a) : "l"(p));
    return a;
}
#define SW(o) ((o) ^ ((((uint32_t)(o)) >> 3) & 0x70u))

#define LDMX4(r, a) \
    asm volatile("ldmatrix.sync.aligned.m8n8.x4.shared.b16 {%0,%1,%2,%3}, [%4];" \
        : "=r"((r)[0]), "=r"((r)[1]), "=r"((r)[2]), "=r"((r)[3]) : "r"(a))

#define MMA16816(c, a, b0, b1) \
    asm volatile("mma.sync.aligned.m16n8k16.row.col.f32.f16.f16.f32 " \
        "{%0,%1,%2,%3}, {%4,%5,%6,%7}, {%8,%9}, {%0,%1,%2,%3};" \
        : "+f"((c)[0]), "+f"((c)[1]), "+f"((c)[2]), "+f"((c)[3]) \
        : "r"((a)[0]), "r"((a)[1]), "r"((a)[2]), "r"((a)[3]), "r"(b0), "r"(b1))

#define CP16(dst, src) \
    asm volatile("cp.async.cg.shared.global [%0], [%1], 16;" :: "r"(dst), "l"(src))
#define CP_COMMIT() asm volatile("cp.async.commit_group;" ::: "memory")
#define CP_WAIT0()  asm volatile("cp.async.wait_group 0;" ::: "memory")

// monotonic float -> uint map (order preserving; nonzero for all non-NaN inputs)
__device__ __forceinline__ uint32_t fmono(float f) {
    uint32_t u = __float_as_uint(f);
    return (u & 0x80000000u) ? ~u : (u | 0x80000000u);
}

// ---------------- fused prep: blocks [0,256) = emb prep; [256,1280) = z transpose ----------------
__global__ void k_prep(const float* __restrict__ emb, const float* __restrict__ z) {
    __shared__ float sm[32 * 257];
    int tid = threadIdx.x;
    if (blockIdx.x < 256) {
        float (*tile)[257] = (float(*)[257])sm;
        int k0 = blockIdx.x * 32;
        for (int i = tid; i < 32 * Dv; i += 256) {
            int r = i >> 8, d = i & 255;
            tile[r][d] = emb[(size_t)(k0 + r) * Dv + d];
        }
        if (tid < 64) g_key[blockIdx.x * 64 + tid] = 0ull;
        __syncthreads();
        {
            int c = tid >> 3, p = tid & 7;
            const float* row = &tile[c][p * 32];
            float s = 0.f;
#pragma unroll
            for (int d = 0; d < 32; d++) s += row[d] * row[d];
#pragma unroll
            for (int o = 4; o; o >>= 1) s += __shfl_xor_sync(0xffffffffu, s, o);
            if (p == 0) {
                g_h[k0 + c] = 0.5f * s;
                g_cnt[k0 + c] = 0.f;
            }
        }
        if (blockIdx.x == 0 && tid == 0) g_nflag = 0;
        for (int i = tid; i < 32 * 128; i += 256) {
            int r = i >> 7, d2 = i & 127;
            __half2 h2 = __floats2half2_rn(tile[r][d2 * 2], tile[r][d2 * 2 + 1]);
            ((__half2*)g_ehi)[(size_t)(k0 + r) * (Dv / 2) + d2] = h2;
        }
        {
            int tx = tid & 31, ty = tid >> 5;
#pragma unroll 4
            for (int j = 0; j < 32; j++) {
                int d = ty * 32 + j;
                g_eT[(size_t)d * Kv + k0 + tx] = tile[tx][d];
            }
        }
    } else {
        float (*tile)[65] = (float(*)[65])sm;
        int idx = blockIdx.x - 256;
        int t0 = (idx & 15) * 64, d0 = ((idx >> 4) & 3) * 64, b = idx >> 6;
        const float* src = z + ((size_t)b * Dv + d0) * Tv + t0;
        for (int i = tid; i < 1024; i += 256) {
            int dd = i >> 4, tq = i & 15;
            float4 v = *(const float4*)(src + (size_t)dd * Tv + tq * 4);
            tile[dd][tq * 4 + 0] = v.x; tile[dd][tq * 4 + 1] = v.y;
            tile[dd][tq * 4 + 2] = v.z; tile[dd][tq * 4 + 3] = v.w;
        }
        __syncthreads();
        int n0 = b * Tv + t0;
        for (int i = tid; i < 1024; i += 256) {
            int tt = i >> 4, dq = i & 15;
            float y[4];
#pragma unroll
            for (int c = 0; c < 4; c++) y[c] = tile[dq * 4 + c][tt];
            size_t o = (size_t)(n0 + tt) * Dv + d0 + dq * 4;
            *(float4*)(g_xf + o) = make_float4(y[0], y[1], y[2], y[3]);
            __half hi[4];
#pragma unroll
            for (int c = 0; c < 4; c++) hi[c] = __float2half_rn(y[c]);
            *(uint2*)(g_xhi + o) = *(uint2*)hi;
        }
    }
}

// ---------------- main: 64-row CTAs, 2 CTAs/SM, 32x64 warp tiles over 256-code iterations ----------------
// Warp w: row-group rg=w>>2 (rows rg*32..+31), col-group cg=w&3 (codes it*256 + cg*64..+63).
// smem: A [0,32K): 4 d-blocks x [64r][64d] SW128 (8KB each);
//       B double buffer [32K,96K): 2 x 32KB = [256 codes][64 d] per cc chunk.
#define SM_B   32768
#define SMEM_SZ (98304 + 2048)

__global__ __launch_bounds__(256, 2) void k_mma() {
    extern __shared__ char smraw[];
    uint32_t raw = smem_u32(smraw);
    uint32_t sb = (raw + 1023u) & ~1023u;
    char* smp = smraw + (sb - raw);
    const int tid = threadIdx.x, wid = tid >> 5, lane = tid & 31;
    const int n0 = blockIdx.x * 64;
    const int rg = wid >> 2, cg = wid & 3;
    const int g = lane >> 2, tg = lane & 3;

    // stage A: Xhi, 4 d-blocks of [64r][64 fp16] SW128 (2048 16B units)
    for (int u = tid; u < 2048; u += 256) {
        int c = u >> 9, r = (u >> 3) & 63, q = u & 7;
        size_t so = (size_t)(n0 + r) * Dv + c * 64 + q * 8;
        *(uint4*)(smp + c * 8192 + SW(r * 128 + q * 16)) = *(const uint4*)(g_xhi + so);
    }

    const int m = lane >> 3, j7 = lane & 7;
    uint32_t arow[2];
#pragma unroll
    for (int s = 0; s < 2; s++)
        arow[s] = (uint32_t)(rg * 32 + s * 16 + (m & 1) * 8 + j7) * 128;
    const uint32_t ach   = (uint32_t)(lane >> 4) * 16;
    // B lane base: code row (within 256-code chunk) = cg*64 + nt*16 + (m>>1)*8 + j7
    const uint32_t bbase = (uint32_t)(cg * 64 + (m >> 1) * 8 + j7) * 128 + (uint32_t)(m & 1) * 16;

    // cp.async 32KB chunk loader: gidx = it*4 + cc -> buf gidx&1
    // chunk = [256 codes of it][64 d of block cc], SW128 rows of 128B
    auto load_chunk = [&](int gidx) {
        int it = gidx >> 2, cc = gidx & 3;
        uint32_t bb = sb + SM_B + (gidx & 1) * 32768;
        const __half* sh = g_ehi + (size_t)(it * 256) * Dv + cc * 64;
#pragma unroll
        for (int j = 0; j < 8; j++) {
            int u = tid + 256 * j;             // 0..2047 16B units
            int row = u >> 3, q = u & 7;       // row 0..255
            CP16(bb + SW(row * 128 + q * 16), sh + (size_t)row * Dv + q * 8);
        }
    };

    load_chunk(0);
    CP_COMMIT();
    CP_WAIT0();
    __syncthreads();

    // trackers: 4 rows per thread: r = s*2+half -> row rg*32 + s*16 + g + half*8
    float best[4]  = { -3.4e38f, -3.4e38f, -3.4e38f, -3.4e38f };
    float best2[4] = { -3.4e38f, -3.4e38f, -3.4e38f, -3.4e38f };
    int   bk[4]    = { 0, 0, 0, 0 };

    uint32_t A[2][2][4];   // [buf][stripe][4]
    uint32_t B[4][4];      // [ntile][4] (single buffered)

#pragma unroll 1
    for (int it = 0; it < 32; it++) {
        float acc[16][4];
#pragma unroll
        for (int i = 0; i < 16; i++)
#pragma unroll
            for (int q = 0; q < 4; q++) acc[i][q] = 0.f;

#pragma unroll 1
        for (int cc = 0; cc < 4; cc++) {
            int gi = it * 4 + cc;
            if (gi < 127) { load_chunk(gi + 1); CP_COMMIT(); }

            const uint32_t abase = sb + cc * 8192;
            const uint32_t bB = sb + SM_B + (gi & 1) * 32768;

            // preload ds=0 A fragments
#pragma unroll
            for (int s = 0; s < 2; s++)
                LDMX4(A[0][s], abase + SW(arow[s] + ach));

#pragma unroll
            for (int ds = 0; ds < 4; ds++) {
                const int ab = ds & 1;
                // load B fragments for this ds (4 n-tiles of 16 codes)
#pragma unroll
                for (int nt = 0; nt < 4; nt++)
                    LDMX4(B[nt], bB + SW(bbase + nt * 2048 + ds * 32));
                // prefetch next A fragments
                if (ds < 3) {
#pragma unroll
                    for (int s = 0; s < 2; s++)
                        LDMX4(A[ab ^ 1][s], abase + SW(arow[s] + (ds + 1) * 32 + ach));
                }
                // 16 MMAs
#pragma unroll
                for (int s = 0; s < 2; s++)
#pragma unroll
                    for (int nt = 0; nt < 4; nt++) {
                        MMA16816(acc[s * 8 + nt * 2],     A[ab][s], B[nt][0], B[nt][1]);
                        MMA16816(acc[s * 8 + nt * 2 + 1], A[ab][s], B[nt][2], B[nt][3]);
                    }
            }
            if (gi < 127) CP_WAIT0();
            __syncthreads();
        }

        // epilogue: fold this 256-code iteration (64 codes for this warp) into trackers
#pragma unroll
        for (int s = 0; s < 2; s++)
#pragma unroll
            for (int nt = 0; nt < 4; nt++)
#pragma unroll
                for (int j = 0; j < 2; j++) {
                    int t = s * 8 + nt * 2 + j;
                    int col = it * 256 + cg * 64 + nt * 16 + j * 8 + 2 * tg;
                    float h0 = __ldg(g_h + col), h1 = __ldg(g_h + col + 1);
                    int r0 = s * 2, r1 = s * 2 + 1;
                    float v00 = acc[t][0] - h0, v01 = acc[t][1] - h1;
                    float v10 = acc[t][2] - h0, v11 = acc[t][3] - h1;
                    if (v00 > best[r0]) { best2[r0] = best[r0]; best[r0] = v00; bk[r0] = col; }
                    else if (v00 > best2[r0]) best2[r0] = v00;
                    if (v01 > best[r0]) { best2[r0] = best[r0]; best[r0] = v01; bk[r0] = col + 1; }
                    else if (v01 > best2[r0]) best2[r0] = v01;
                    if (v10 > best[r1]) { best2[r1] = best[r1]; best[r1] = v10; bk[r1] = col; }
                    else if (v10 > best2[r1]) best2[r1] = v10;
                    if (v11 > best[r1]) { best2[r1] = best[r1]; best[r1] = v11; bk[r1] = col + 1; }
                    else if (v11 > best2[r1]) best2[r1] = v11;
                }
    }

    // reduce across the 4 lanes (tg) sharing each row
#pragma unroll
    for (int r = 0; r < 4; r++) {
#pragma unroll
        for (int o = 1; o <= 2; o <<= 1) {
            float ob = __shfl_xor_sync(0xffffffffu, best[r], o);
            float os = __shfl_xor_sync(0xffffffffu, best2[r], o);
            int   ok = __shfl_xor_sync(0xffffffffu, bk[r], o);
            if (ob > best[r] || (ob == best[r] && ok < bk[r])) {
                best2[r] = fmaxf(best[r], os);
                best[r] = ob; bk[r] = ok;
            } else {
                best2[r] = fmaxf(best2[r], ob);
            }
        }
    }

    // cross-warp (col-group) merge via smem: fb/fs/fk [4][64]
    __syncthreads();
    float* fb = (float*)smp;
    float* fs = fb + 256;
    int*   fk = (int*)(fs + 256);
    if (tg == 0) {
#pragma unroll
        for (int r = 0; r < 4; r++) {
            int row = rg * 32 + (r >> 1) * 16 + g + (r & 1) * 8;
            fb[cg * 64 + row] = best[r];
            fs[cg * 64 + row] = best2[r];
            fk[cg * 64 + row] = bk[r];
        }
    }
    __syncthreads();
    if (tid < 64) {
        float bb = fb[tid], ss = fs[tid];
        int kk = fk[tid];
#pragma unroll
        for (int c2 = 1; c2 < 4; c2++) {
            float ob = fb[c2 * 64 + tid], os = fs[c2 * 64 + tid];
            int ok = fk[c2 * 64 + tid];
            if (ob > bb || (ob == bb && ok < kk)) { ss = fmaxf(bb, os); bb = ob; kk = ok; }
            else ss = fmaxf(ss, ob);
        }
        int n = n0 + tid;
        g_idx[n] = kk;
        if (bb - ss < TAU) {
            int pos = atomicAdd(&g_nflag, 1);
            g_flags[pos] = n;
        }
    }
}

// ---------------- rescore: (16-row batch) x (K/16 slice = 512 codes) per work item ----------------
#define RB 16
__global__ __launch_bounds__(256, 2) void k_rescore() {
    __shared__ float sx[RB][Dv];
    __shared__ int   sn[RB];
    int tid = threadIdx.x, lane = tid & 31;
    int nf = g_nflag; if (nf > Nv) nf = Nv;
    if (nf <= 0) return;
    int nbatch = (nf + RB - 1) / RB;
    int nwork = nbatch * 16;
    for (int w = blockIdx.x; w < nwork; w += gridDim.x) {
        int bi = w >> 4, ks = w & 15;
        int r0 = bi * RB;
        int nr = nf - r0; if (nr > RB) nr = RB;
        if (tid < RB) sn[tid] = g_flags[r0 + (tid < nr ? tid : 0)];
        __syncthreads();
        for (int i = tid; i < RB * (Dv / 4); i += 256) {
            int r = i >> 6, d = i & 63;
            *(float4*)&sx[r][d * 4] = *(const float4*)(g_xf + (size_t)sn[r] * Dv + d * 4);
        }
        __syncthreads();

        const int kA = ks * 512 + tid;
        const int kB = kA + 256;
        const float* epA = g_eT + kA;
        const float* epB = g_eT + kB;
        float sA[RB], sB[RB];
#pragma unroll
        for (int r = 0; r < RB; r++) { sA[r] = 0.f; sB[r] = 0.f; }

        float ea[2][4], eb[2][4];
#pragma unroll
        for (int c = 0; c < 4; c++) {
            ea[0][c] = epA[(size_t)c * Kv];
            eb[0][c] = epB[(size_t)c * Kv];
        }
#pragma unroll 2
        for (int d4 = 0; d4 < 64; d4++) {
            int pb = d4 & 1;
            if (d4 < 63) {
#pragma unroll
                for (int c = 0; c < 4; c++) {
                    ea[pb ^ 1][c] = epA[(size_t)((d4 + 1) * 4 + c) * Kv];
                    eb[pb ^ 1][c] = epB[(size_t)((d4 + 1) * 4 + c) * Kv];
                }
            }
#pragma unroll
            for (int r = 0; r < RB; r++) {
                float4 xv = *(const float4*)&sx[r][d4 * 4];
                sA[r] = fmaf(xv.x, ea[pb][0], fmaf(xv.y, ea[pb][1],
                          fmaf(xv.z, ea[pb][2], fmaf(xv.w, ea[pb][3], sA[r]))));
                sB[r] = fmaf(xv.x, eb[pb][0], fmaf(xv.y, eb[pb][1],
                          fmaf(xv.z, eb[pb][2], fmaf(xv.w, eb[pb][3], sB[r]))));
            }
        }

        float hA = g_h[kA], hB = g_h[kB];
#pragma unroll 1
        for (int r = 0; r < RB; r++) {
            if (r >= nr) break;
            float vA = sA[r] - hA, vB = sB[r] - hB;
            float v; int kk;
            if (vA >= vB) { v = vA; kk = kA; } else { v = vB; kk = kB; }
            unsigned long long key = ((unsigned long long)fmono(v) << 32)
                                   | (unsigned long long)(0xFFFFFFFFu - (uint32_t)kk);
#pragma unroll
            for (int o = 16; o; o >>= 1) {
                unsigned long long ok = __shfl_xor_sync(0xffffffffu, key, o);
                if (ok > key) key = ok;
            }
            if (lane == 0) atomicMax(&g_key[sn[r]], key);
        }
        __syncthreads();
    }
}

// ---------------- post: decode keys + exact g_m/xsq + histogram + scatter ----------------
__global__ void k_post(const float* __restrict__ emb, float* __restrict__ out) {
    __shared__ float tile[32][257];
    __shared__ int sidx[32];
    int n0 = blockIdx.x * 32;
    int b = n0 >> 10, t0 = n0 & 1023;
    int tid = threadIdx.x;
    if (tid < 32) {
        int n = n0 + tid;
        unsigned long long key = g_key[n];
        sidx[tid] = key ? (int)(0xFFFFFFFFu - (uint32_t)(key & 0xFFFFFFFFull))
                        : g_idx[n];
    }
    __syncthreads();
    for (int i = tid; i < 32 * Dv; i += 256) {
        int r = i >> 8, d = i & 255;
        tile[r][d] = emb[(size_t)sidx[r] * Dv + d];
    }
    __syncthreads();

    int w = tid >> 5, lane = tid & 31;
#pragma unroll 1
    for (int j = 0; j < 4; j++) {
        int r = w * 4 + j;
        int n = n0 + r;
        const float* x = g_xf + (size_t)n * Dv + lane * 8;
        float4 x0 = *(const float4*)(x), x1 = *(const float4*)(x + 4);
        const float* e = &tile[r][lane * 8];
        float s = x0.x * e[0] + x0.y * e[1] + x0.z * e[2] + x0.w * e[3]
                + x1.x * e[4] + x1.y * e[5] + x1.z * e[6] + x1.w * e[7];
        float q = x0.x * x0.x + x0.y * x0.y + x0.z * x0.z + x0.w * x0.w
                + x1.x * x1.x + x1.y * x1.y + x1.z * x1.z + x1.w * x1.w;
#pragma unroll
        for (int t = 16; t; t >>= 1) {
            s += __shfl_xor_sync(0xffffffffu, s, t);
            q += __shfl_xor_sync(0xffffffffu, q, t);
        }
        if (lane == 0) {
            g_m[n] = s - g_h[sidx[r]];
            g_xsq[n] = q;
            atomicAdd(&g_cnt[sidx[r]], 1.0f);
        }
    }

    float* ob = out + (size_t)b * Dv * Tv + t0;
    for (int i = tid; i < 32 * Dv; i += 256) {
        int d = i >> 5, r = i & 31;
        ob[(size_t)d * Tv + r] = tile[r][d];
    }
}

// ---------------- scalars: parallel partials + tiny finish ----------------
__global__ void k_final1() {
    __shared__ double sd[256];
    int tid = threadIdx.x, bid = blockIdx.x;
    int n = bid * 256 + tid;
    double s = (double)g_xsq[n] - 2.0 * (double)g_m[n];
    double e = 0.0;
    if (tid < 128) {
        int k = bid * 128 + tid;
        double p = (double)g_cnt[k] * (1.0 / (double)Nv);
        e = p * log(p + 1e-10);
    }
    sd[tid] = s; __syncthreads();
    for (int o = 128; o; o >>= 1) { if (tid < o) sd[tid] += sd[tid + o]; __syncthreads(); }
    if (tid == 0) g_ps[bid] = sd[0];
    __syncthreads();
    sd[tid] = e; __syncthreads();
    for (int o = 128; o; o >>= 1) { if (tid < o) sd[tid] += sd[tid + o]; __syncthreads(); }
    if (tid == 0) g_pe[bid] = sd[0];
}

__global__ void k_final2(float* __restrict__ out, int out_size) {
    if (threadIdx.x == 0 && out_size >= BDT + 2) {
        double s = 0.0, e = 0.0;
        for (int i = 0; i < 64; i++) { s += g_ps[i]; e += g_pe[i]; }
        out[BDT]     = (float)(0.25 * s / ((double)Nv * (double)Dv));
        out[BDT + 1] = (float)exp(-e);
    }
}

// ---------------- launch ----------------
extern "C" void kernel_launch(void* const* d_in, const int* in_sizes, int n_in,
                              void* d_out, int out_size) {
    const float* z   = (const float*)d_in[0];
    const float* emb = (const float*)d_in[1];
    float* out = (float*)d_out;

    cudaFuncSetAttribute(k_mma, cudaFuncAttributeMaxDynamicSharedMemorySize, SMEM_SZ);

    k_prep   <<<1280, 256>>>(emb, z);
    k_mma    <<<Nv / 64, 256, SMEM_SZ>>>();
    k_rescore<<<256, 256>>>();
    k_post   <<<Nv / 32, 256>>>(emb, out);
    k_final1 <<<64, 256>>>();
    k_final2 <<<1, 32>>>(out, out_size);
}